// round 7
// baseline (speedup 1.0000x reference)
#include <cuda_runtime.h>
#include <math.h>
#include <stdint.h>

// Shapes
#define BATCH   32
#define SLEN    576
#define EMB_    512
#define NHEAD   8
#define HD      64
#define TOK     (BATCH*SLEN) // 18432
#define IMGW    384
#define KCONV   768

// -------- scratch (device globals) --------
__device__ float g_h  [TOK*EMB_];   // patch embeddings
__device__ float g_ctx[TOK*EMB_];   // att @ h
__device__ float g_Gt [HD*HD];      // Gt[n][k] = 0.125 * sum_e wq[e,k]*wk[e,n]
__device__ float g_WvoT[EMB_*EMB_];

// ---------------- tf32 helpers ----------------
__device__ __forceinline__ uint32_t f2tf(float x) {
    uint32_t r; asm("cvt.rna.tf32.f32 %0, %1;" : "=r"(r) : "f"(x)); return r;
}
__device__ __forceinline__ void mma_tf32(float* c, const uint32_t* a, uint32_t b0, uint32_t b1) {
    asm volatile(
        "mma.sync.aligned.m16n8k8.row.col.f32.tf32.tf32.f32 "
        "{%0,%1,%2,%3}, {%4,%5,%6,%7}, {%8,%9}, {%0,%1,%2,%3};\n"
        : "+f"(c[0]), "+f"(c[1]), "+f"(c[2]), "+f"(c[3])
        : "r"(a[0]), "r"(a[1]), "r"(a[2]), "r"(a[3]), "r"(b0), "r"(b1));
}
__device__ __forceinline__ void cp_async16(void* smem, const void* gmem) {
    uint32_t s = (uint32_t)__cvta_generic_to_shared(smem);
    asm volatile("cp.async.cg.shared.global [%0], [%1], 16;\n" :: "r"(s), "l"(gmem));
}
#define CP_COMMIT() asm volatile("cp.async.commit_group;\n")
#define CP_WAIT(n)  asm volatile("cp.async.wait_group %0;\n" :: "n"(n))

// =================================================================
// Weight folding preps (tiny)
// =================================================================
__global__ void prep_G(const float* __restrict__ wq, const float* __restrict__ wk) {
    int dp = blockIdx.x, d = threadIdx.x;
    float s = 0.f;
    #pragma unroll 8
    for (int e = 0; e < 64; e++) s += wq[e*64 + d] * wk[e*64 + dp];
    g_Gt[dp*64 + d] = 0.125f * s;
}
__global__ void prep_Wvo(const float* __restrict__ wv, const float* __restrict__ wo) {
    int f = blockIdx.x, hd = threadIdx.x;
    int h = hd >> 6, d = hd & 63;
    float s = 0.f;
    #pragma unroll 8
    for (int e = 0; e < 64; e++) s += wv[e*64 + d] * wo[(size_t)f*512 + h*64 + e];
    g_WvoT[(size_t)f*512 + hd] = s;
}

// =================================================================
// tf32 MMA GEMM (unchanged): C = A.B^T + bias, BM=BN=128, BK=32
// (stride 36 == 4 mod 32 -> fragment loads already conflict-free)
// =================================================================
#define GEMM_SMEM (2*128*36*2*4)   // 73728 B

template<bool CONV>
__global__ __launch_bounds__(256) void mma_gemm(const float* __restrict__ Ain,
                                                const float* __restrict__ Bin,
                                                const float* __restrict__ bias,
                                                float* __restrict__ Cout, int K) {
    extern __shared__ float sm[];
    float* As = sm;
    float* Bs = sm + 2*128*36;

    const int tid = threadIdx.x;
    const int lane = tid & 31;
    const int w = tid >> 5, wm = w & 1, wn = w >> 1;
    const int g = lane >> 2, tig = lane & 3;
    const int m0 = blockIdx.y * 128, n0 = blockIdx.x * 128;

    const float* A = CONV ? Ain : g_ctx;
    const float* B = CONV ? Bin : g_WvoT;

    int lrow[4], lkc[4];
    const float* abase[4];
    const float* bbase[4];
    #pragma unroll
    for (int i = 0; i < 4; i++) {
        int v = tid + i*256;
        int row = v >> 3, kc = v & 7;
        lrow[i] = row; lkc[i] = kc;
        if (CONV) {
            int m = m0 + row;
            int bb = m / 576, p = m % 576;
            int py = p / 24, px = p % 24;
            abase[i] = A + (size_t)bb*3*IMGW*IMGW + (size_t)(py*16)*IMGW + px*16;
        } else {
            abase[i] = A + (size_t)(m0 + row)*512 + kc*4;
        }
        bbase[i] = B + (size_t)(n0 + row)*K + kc*4;
    }

    auto load_tiles = [&](int buf, int k0) {
        #pragma unroll
        for (int i = 0; i < 4; i++) {
            const float* ga;
            if (CONV) {
                int kg = k0 + lkc[i]*4;
                int c = kg >> 8, rem = kg & 255;
                int dy = rem >> 4, dx = rem & 15;
                ga = abase[i] + (size_t)c*(IMGW*IMGW) + dy*IMGW + dx;
            } else {
                ga = abase[i] + k0;
            }
            cp_async16(&As[buf*4608 + lrow[i]*36 + lkc[i]*4], ga);
            cp_async16(&Bs[buf*4608 + lrow[i]*36 + lkc[i]*4], bbase[i] + k0);
        }
    };

    float acc[4][4][4] = {};

    load_tiles(0, 0);
    CP_COMMIT();
    const int nk = K / 32;
    for (int t = 0; t < nk; t++) {
        int buf = t & 1;
        if (t + 1 < nk) load_tiles(buf ^ 1, (t+1)*32);
        CP_COMMIT();
        CP_WAIT(1);
        __syncthreads();

        const float* Ab = &As[buf*4608];
        const float* Bb = &Bs[buf*4608];
        #pragma unroll
        for (int ks = 0; ks < 4; ks++) {
            int k = ks * 8;
            uint32_t af[4][4], bf[4][2];
            #pragma unroll
            for (int i = 0; i < 4; i++) {
                int r = wm*64 + i*16 + g;
                af[i][0] = f2tf(Ab[(r  )*36 + k + tig]);
                af[i][1] = f2tf(Ab[(r+8)*36 + k + tig]);
                af[i][2] = f2tf(Ab[(r  )*36 + k + tig + 4]);
                af[i][3] = f2tf(Ab[(r+8)*36 + k + tig + 4]);
            }
            #pragma unroll
            for (int j = 0; j < 4; j++) {
                int n = wn*32 + j*8 + g;
                bf[j][0] = f2tf(Bb[n*36 + k + tig]);
                bf[j][1] = f2tf(Bb[n*36 + k + tig + 4]);
            }
            #pragma unroll
            for (int i = 0; i < 4; i++)
                #pragma unroll
                for (int j = 0; j < 4; j++)
                    mma_tf32(acc[i][j], af[i], bf[j][0], bf[j][1]);
        }
        __syncthreads();
    }

    float* C = CONV ? g_h : Cout;
    #pragma unroll
    for (int i = 0; i < 4; i++) {
        int r = m0 + wm*64 + i*16 + g;
        #pragma unroll
        for (int j = 0; j < 4; j++) {
            int cc = n0 + wn*32 + j*8 + tig*2;
            float2 v0 = make_float2(acc[i][j][0] + bias[cc], acc[i][j][1] + bias[cc+1]);
            float2 v1 = make_float2(acc[i][j][2] + bias[cc], acc[i][j][3] + bias[cc+1]);
            *(float2*)&C[(size_t)r*512 + cc] = v0;
            *(float2*)&C[(size_t)(r+8)*512 + cc] = v1;
        }
    }
}

// =================================================================
// Flash attention, tf32 MMA, fused Q-proj, N-split warps,
// DUAL-LAYOUT K tiles for conflict-free smem:
//   K68 (stride 68 == 4 mod 32): S-phase B loads  (8-row pattern)
//   K72 (stride 72 == 8 mod 32): PV-phase B loads (4-row pattern)
//   R1  (stride 68): P/Q region -> PV A loads conflict-free
// =================================================================
#define A68 68
#define A72 72
// R1 96x68 | K68 2x64x68 | K72 2x64x72 | Msm 96x2 | Ssm 96x2
#define ATTN_SMEM ((96*A68 + 2*64*A68 + 2*64*A72 + 96*2 + 96*2)*4)  // 99328 B

__global__ __launch_bounds__(192, 2) void attn_mma() {
    extern __shared__ float sm[];
    float* R1  = sm;                          // [96][68]: H -> Q bits -> P bits
    float* K68 = sm + 96*A68;                 // [2][64][68]; buf1 holds G in prologue
    float* K72 = K68 + 2*64*A68;              // [2][64][72]
    float* Msm = K72 + 2*64*A72;              // [96][2]
    float* Ssm = Msm + 96*2;                  // [96][2]
    uint32_t* Rb = (uint32_t*)R1;

    const int qt = blockIdx.x, hh = blockIdx.y, b = blockIdx.z;
    const int tid = threadIdx.x;
    const int w = tid >> 5, lane = tid & 31;
    const int wm = w >> 1, wn = w & 1;
    const int g = lane >> 2, tig = lane & 3;
    const size_t rowbase = (size_t)(b*SLEN)*EMB_ + hh*HD;
    const int rr[2] = { wm*32 + g, wm*32 + 16 + g };

    auto loadKV = [&](int buf, int kt) {
        const float* kb = g_h + rowbase + (size_t)(kt*64)*EMB_;
        for (int v = tid; v < 64*16; v += 192) {
            int r = v >> 4, cq = (v & 15) * 4;
            const float* src = kb + (size_t)r*EMB_ + cq;
            cp_async16(&K68[buf*64*A68 + r*A68 + cq], src);
            cp_async16(&K72[buf*64*A72 + r*A72 + cq], src);
        }
    };

    // ---- prologue loads: KV tile 0 -> buf0 (both), H -> R1, G -> K68 buf1 ----
    loadKV(0, 0);
    {
        const float* hb = g_h + rowbase + (size_t)(qt*96)*EMB_;
        for (int v = tid; v < 96*16; v += 192) {
            int r = v >> 4, cq = (v & 15) * 4;
            cp_async16(&R1[r*A68 + cq], hb + (size_t)r*EMB_ + cq);
        }
        for (int v = tid; v < 64*16; v += 192) {
            int r = v >> 4, cq = (v & 15) * 4;
            cp_async16(&K68[64*A68 + r*A68 + cq], g_Gt + r*64 + cq);
        }
    }
    CP_COMMIT();
    CP_WAIT(0);
    __syncthreads();

    // ---- Q = H @ G (warp: 32 rows x 32 cols) ----
    {
        float qc[2][4][4] = {};
        const float* Gd = &K68[64*A68];
        #pragma unroll
        for (int ks = 0; ks < 8; ks++) {
            int k = ks*8;
            uint32_t ha[2][4];
            #pragma unroll
            for (int i = 0; i < 2; i++) {
                ha[i][0] = f2tf(R1[(rr[i]  )*A68 + k + tig]);
                ha[i][1] = f2tf(R1[(rr[i]+8)*A68 + k + tig]);
                ha[i][2] = f2tf(R1[(rr[i]  )*A68 + k + tig + 4]);
                ha[i][3] = f2tf(R1[(rr[i]+8)*A68 + k + tig + 4]);
            }
            #pragma unroll
            for (int j = 0; j < 4; j++) {
                int n = wn*32 + j*8 + g;
                uint32_t b0 = f2tf(Gd[n*A68 + k + tig]);
                uint32_t b1 = f2tf(Gd[n*A68 + k + tig + 4]);
                mma_tf32(qc[0][j], ha[0], b0, b1);
                mma_tf32(qc[1][j], ha[1], b0, b1);
            }
        }
        __syncthreads();   // everyone done reading H (R1) and G (K68 buf1)
        #pragma unroll
        for (int i = 0; i < 2; i++)
            #pragma unroll
            for (int j = 0; j < 4; j++) {
                int cc = wn*32 + j*8 + tig*2;
                uint2 u0 = make_uint2(f2tf(qc[i][j][0]), f2tf(qc[i][j][1]));
                uint2 u1 = make_uint2(f2tf(qc[i][j][2]), f2tf(qc[i][j][3]));
                *(uint2*)&Rb[(rr[i]  )*A68 + cc] = u0;
                *(uint2*)&Rb[(rr[i]+8)*A68 + cc] = u1;
            }
        __syncthreads();   // full-width Q bits visible
    }

    // Q fragments register-resident (full width, both m-tiles)
    uint32_t aq[2][8][4];
    #pragma unroll
    for (int ks = 0; ks < 8; ks++) {
        int k = ks*8;
        #pragma unroll
        for (int i = 0; i < 2; i++) {
            aq[i][ks][0] = Rb[(rr[i]  )*A68 + k + tig];
            aq[i][ks][1] = Rb[(rr[i]+8)*A68 + k + tig];
            aq[i][ks][2] = Rb[(rr[i]  )*A68 + k + tig + 4];
            aq[i][ks][3] = Rb[(rr[i]+8)*A68 + k + tig + 4];
        }
    }

    float oacc[2][4][4] = {};
    float m_[2][2], l_[2][2];
    #pragma unroll
    for (int i = 0; i < 2; i++) { m_[i][0] = m_[i][1] = -3.0e38f; l_[i][0] = l_[i][1] = 0.f; }

    for (int kt = 0; kt < 9; kt++) {
        int buf = kt & 1;
        CP_WAIT(0);
        __syncthreads();                      // both raw copies ready

        if (kt + 1 < 9) { loadKV(buf ^ 1, kt + 1); CP_COMMIT(); }

        // ---- convert both copies to tf32 bits in place (clean float4) ----
        {
            float* Ka = &K68[buf*64*A68];
            float* Kb = &K72[buf*64*A72];
            uint32_t* Ua = (uint32_t*)Ka;
            uint32_t* Ub = (uint32_t*)Kb;
            for (int v = tid; v < 64*16; v += 192) {
                int r = v >> 4, c = (v & 15) * 4;
                float4 fa = *(float4*)&Ka[r*A68 + c];
                uint4 ua;
                ua.x = f2tf(fa.x); ua.y = f2tf(fa.y); ua.z = f2tf(fa.z); ua.w = f2tf(fa.w);
                *(uint4*)&Ua[r*A68 + c] = ua;
                float4 fb = *(float4*)&Kb[r*A72 + c];
                uint4 ub;
                ub.x = f2tf(fb.x); ub.y = f2tf(fb.y); ub.z = f2tf(fb.z); ub.w = f2tf(fb.w);
                *(uint4*)&Ub[r*A72 + c] = ub;
            }
        }
        __syncthreads();

        const uint32_t* KS = (const uint32_t*)&K68[buf*64*A68];   // S-phase
        const uint32_t* KV = (const uint32_t*)&K72[buf*64*A72];   // PV-phase

        // ---- S = Q K^T  (B loads conflict-free: bank = g*4+tig) ----
        float sacc[2][4][4] = {};
        #pragma unroll
        for (int ks = 0; ks < 8; ks++) {
            int k = ks*8;
            #pragma unroll
            for (int j = 0; j < 4; j++) {
                int l = wn*32 + j*8 + g;
                uint32_t b0 = KS[l*A68 + k + tig];
                uint32_t b1 = KS[l*A68 + k + tig + 4];
                mma_tf32(sacc[0][j], aq[0][ks], b0, b1);
                mma_tf32(sacc[1][j], aq[1][ks], b0, b1);
            }
        }

        // ---- partial row max, quad-reduce, exchange across wn pair ----
        float pm[2][2];
        #pragma unroll
        for (int i = 0; i < 2; i++) {
            pm[i][0] = fmaxf(fmaxf(sacc[i][0][0], sacc[i][0][1]), fmaxf(sacc[i][1][0], sacc[i][1][1]));
            pm[i][0] = fmaxf(pm[i][0], fmaxf(fmaxf(sacc[i][2][0], sacc[i][2][1]), fmaxf(sacc[i][3][0], sacc[i][3][1])));
            pm[i][1] = fmaxf(fmaxf(sacc[i][0][2], sacc[i][0][3]), fmaxf(sacc[i][1][2], sacc[i][1][3]));
            pm[i][1] = fmaxf(pm[i][1], fmaxf(fmaxf(sacc[i][2][2], sacc[i][2][3]), fmaxf(sacc[i][3][2], sacc[i][3][3])));
            #pragma unroll
            for (int r = 0; r < 2; r++) {
                pm[i][r] = fmaxf(pm[i][r], __shfl_xor_sync(0xffffffffu, pm[i][r], 1));
                pm[i][r] = fmaxf(pm[i][r], __shfl_xor_sync(0xffffffffu, pm[i][r], 2));
            }
        }
        if (tig == 0) {
            #pragma unroll
            for (int i = 0; i < 2; i++) {
                Msm[(rr[i]  )*2 + wn] = pm[i][0];
                Msm[(rr[i]+8)*2 + wn] = pm[i][1];
            }
        }
        __syncthreads();

        float alpha[2][2];
        #pragma unroll
        for (int i = 0; i < 2; i++) {
            #pragma unroll
            for (int r = 0; r < 2; r++) {
                int row = rr[i] + r*8;
                float mt = fmaxf(Msm[row*2], Msm[row*2 + 1]);
                float mnew = fmaxf(m_[i][r], mt);
                alpha[i][r] = __expf(m_[i][r] - mnew);
                m_[i][r] = mnew;
            }
        }

        // ---- p = exp(s-m) -> R1 (uint2 stores), partial sums, exchange ----
        float psum[2][2] = {};
        #pragma unroll
        for (int i = 0; i < 2; i++)
            #pragma unroll
            for (int j = 0; j < 4; j++) {
                int cc = wn*32 + j*8 + tig*2;
                float p0 = __expf(sacc[i][j][0] - m_[i][0]);
                float p1 = __expf(sacc[i][j][1] - m_[i][0]);
                float p2 = __expf(sacc[i][j][2] - m_[i][1]);
                float p3 = __expf(sacc[i][j][3] - m_[i][1]);
                psum[i][0] += p0 + p1;
                psum[i][1] += p2 + p3;
                *(uint2*)&Rb[(rr[i]  )*A68 + cc] = make_uint2(f2tf(p0), f2tf(p1));
                *(uint2*)&Rb[(rr[i]+8)*A68 + cc] = make_uint2(f2tf(p2), f2tf(p3));
            }
        #pragma unroll
        for (int i = 0; i < 2; i++)
            #pragma unroll
            for (int r = 0; r < 2; r++) {
                psum[i][r] += __shfl_xor_sync(0xffffffffu, psum[i][r], 1);
                psum[i][r] += __shfl_xor_sync(0xffffffffu, psum[i][r], 2);
            }
        if (tig == 0) {
            #pragma unroll
            for (int i = 0; i < 2; i++) {
                Ssm[(rr[i]  )*2 + wn] = psum[i][0];
                Ssm[(rr[i]+8)*2 + wn] = psum[i][1];
            }
        }
        __syncthreads();   // P full width + sums visible

        #pragma unroll
        for (int i = 0; i < 2; i++) {
            #pragma unroll
            for (int r = 0; r < 2; r++) {
                int row = rr[i] + r*8;
                l_[i][r] = l_[i][r]*alpha[i][r] + Ssm[row*2] + Ssm[row*2 + 1];
            }
            #pragma unroll
            for (int j = 0; j < 4; j++) {
                oacc[i][j][0] *= alpha[i][0]; oacc[i][j][1] *= alpha[i][0];
                oacc[i][j][2] *= alpha[i][1]; oacc[i][j][3] *= alpha[i][1];
            }
        }

        // ---- O += P V  (A loads bank=g*4+tig clean; B loads bank=tig*8+g clean) ----
        #pragma unroll
        for (int ks = 0; ks < 8; ks++) {
            int k = ks*8;
            uint32_t ap[2][4];
            #pragma unroll
            for (int i = 0; i < 2; i++) {
                ap[i][0] = Rb[(rr[i]  )*A68 + k + tig];
                ap[i][1] = Rb[(rr[i]+8)*A68 + k + tig];
                ap[i][2] = Rb[(rr[i]  )*A68 + k + tig + 4];
                ap[i][3] = Rb[(rr[i]+8)*A68 + k + tig + 4];
            }
            #pragma unroll
            for (int j = 0; j < 4; j++) {
                int d = wn*32 + j*8 + g;
                uint32_t b0 = KV[(k + tig    )*A72 + d];
                uint32_t b1 = KV[(k + tig + 4)*A72 + d];
                mma_tf32(oacc[0][j], ap[0], b0, b1);
                mma_tf32(oacc[1][j], ap[1], b0, b1);
            }
        }
    }

    // ---- epilogue ----
    float* ob = g_ctx + rowbase + (size_t)(qt*96)*EMB_;
    #pragma unroll
    for (int i = 0; i < 2; i++)
        #pragma unroll
        for (int r = 0; r < 2; r++) {
            int row = rr[i] + r*8;
            float inv = 1.0f / l_[i][r];
            #pragma unroll
            for (int j = 0; j < 4; j++) {
                int d = wn*32 + j*8 + tig*2;
                float2 v = make_float2(oacc[i][j][r*2]*inv, oacc[i][j][r*2+1]*inv);
                *(float2*)&ob[(size_t)row*EMB_ + d] = v;
            }
        }
}

// =================================================================
extern "C" void kernel_launch(void* const* d_in, const int* in_sizes, int n_in,
                              void* d_out, int out_size) {
    (void)in_sizes; (void)n_in; (void)out_size;
    const float* x      = (const float*)d_in[0];
    const float* conv_w = (const float*)d_in[1];
    const float* conv_b = (const float*)d_in[2];
    const float* wq     = (const float*)d_in[3];
    const float* wk     = (const float*)d_in[4];
    const float* wv     = (const float*)d_in[5];
    const float* wo     = (const float*)d_in[6];
    const float* bo     = (const float*)d_in[7];
    float* out = (float*)d_out;

    cudaFuncSetAttribute(mma_gemm<true>,  cudaFuncAttributeMaxDynamicSharedMemorySize, GEMM_SMEM);
    cudaFuncSetAttribute(mma_gemm<false>, cudaFuncAttributeMaxDynamicSharedMemorySize, GEMM_SMEM);
    cudaFuncSetAttribute(attn_mma, cudaFuncAttributeMaxDynamicSharedMemorySize, ATTN_SMEM);

    prep_G  <<<64, 64>>>(wq, wk);
    prep_Wvo<<<512, 512>>>(wv, wo);
    mma_gemm<true><<<dim3(4, 144), 256, GEMM_SMEM>>>(x, conv_w, conv_b, nullptr, KCONV);
    attn_mma<<<dim3(6, NHEAD, BATCH), 192, ATTN_SMEM>>>();
    mma_gemm<false><<<dim3(4, 144), 256, GEMM_SMEM>>>(nullptr, nullptr, bo, out, EMB_);
}

// round 8
// speedup vs baseline: 1.0431x; 1.0431x over previous
#include <cuda_runtime.h>
#include <math.h>
#include <stdint.h>

// Shapes
#define BATCH   32
#define SLEN    576
#define EMB_    512
#define NHEAD   8
#define HD      64
#define TOK     (BATCH*SLEN) // 18432
#define IMGW    384
#define KCONV   768

// -------- scratch (device globals) --------
__device__ float g_h  [TOK*EMB_];   // patch embeddings
__device__ float g_ctx[TOK*EMB_];   // att @ h
__device__ float g_Gt [HD*HD];      // Gt[n][k] = 0.125 * sum_e wq[e,k]*wk[e,n]
__device__ float g_WvoT[EMB_*EMB_];

// ---------------- tf32 helpers ----------------
__device__ __forceinline__ uint32_t f2tf(float x) {
    uint32_t r; asm("cvt.rna.tf32.f32 %0, %1;" : "=r"(r) : "f"(x)); return r;
}
__device__ __forceinline__ void mma_tf32(float* c, const uint32_t* a, uint32_t b0, uint32_t b1) {
    asm volatile(
        "mma.sync.aligned.m16n8k8.row.col.f32.tf32.tf32.f32 "
        "{%0,%1,%2,%3}, {%4,%5,%6,%7}, {%8,%9}, {%0,%1,%2,%3};\n"
        : "+f"(c[0]), "+f"(c[1]), "+f"(c[2]), "+f"(c[3])
        : "r"(a[0]), "r"(a[1]), "r"(a[2]), "r"(a[3]), "r"(b0), "r"(b1));
}
__device__ __forceinline__ void cp_async16(void* smem, const void* gmem) {
    uint32_t s = (uint32_t)__cvta_generic_to_shared(smem);
    asm volatile("cp.async.cg.shared.global [%0], [%1], 16;\n" :: "r"(s), "l"(gmem));
}
#define CP_COMMIT() asm volatile("cp.async.commit_group;\n")
#define CP_WAIT(n)  asm volatile("cp.async.wait_group %0;\n" :: "n"(n))

// =================================================================
// Weight folding preps (tiny)
// =================================================================
__global__ void prep_G(const float* __restrict__ wq, const float* __restrict__ wk) {
    int dp = blockIdx.x, d = threadIdx.x;
    float s = 0.f;
    #pragma unroll 8
    for (int e = 0; e < 64; e++) s += wq[e*64 + d] * wk[e*64 + dp];
    g_Gt[dp*64 + d] = 0.125f * s;
}
__global__ void prep_Wvo(const float* __restrict__ wv, const float* __restrict__ wo) {
    int f = blockIdx.x, hd = threadIdx.x;
    int h = hd >> 6, d = hd & 63;
    float s = 0.f;
    #pragma unroll 8
    for (int e = 0; e < 64; e++) s += wv[e*64 + d] * wo[(size_t)f*512 + h*64 + e];
    g_WvoT[(size_t)f*512 + hd] = s;
}

// =================================================================
// tf32 MMA GEMM (unchanged): C = A.B^T + bias, BM=BN=128, BK=32
// =================================================================
#define GEMM_SMEM (2*128*36*2*4)   // 73728 B

template<bool CONV>
__global__ __launch_bounds__(256) void mma_gemm(const float* __restrict__ Ain,
                                                const float* __restrict__ Bin,
                                                const float* __restrict__ bias,
                                                float* __restrict__ Cout, int K) {
    extern __shared__ float sm[];
    float* As = sm;
    float* Bs = sm + 2*128*36;

    const int tid = threadIdx.x;
    const int lane = tid & 31;
    const int w = tid >> 5, wm = w & 1, wn = w >> 1;
    const int g = lane >> 2, tig = lane & 3;
    const int m0 = blockIdx.y * 128, n0 = blockIdx.x * 128;

    const float* A = CONV ? Ain : g_ctx;
    const float* B = CONV ? Bin : g_WvoT;

    int lrow[4], lkc[4];
    const float* abase[4];
    const float* bbase[4];
    #pragma unroll
    for (int i = 0; i < 4; i++) {
        int v = tid + i*256;
        int row = v >> 3, kc = v & 7;
        lrow[i] = row; lkc[i] = kc;
        if (CONV) {
            int m = m0 + row;
            int bb = m / 576, p = m % 576;
            int py = p / 24, px = p % 24;
            abase[i] = A + (size_t)bb*3*IMGW*IMGW + (size_t)(py*16)*IMGW + px*16;
        } else {
            abase[i] = A + (size_t)(m0 + row)*512 + kc*4;
        }
        bbase[i] = B + (size_t)(n0 + row)*K + kc*4;
    }

    auto load_tiles = [&](int buf, int k0) {
        #pragma unroll
        for (int i = 0; i < 4; i++) {
            const float* ga;
            if (CONV) {
                int kg = k0 + lkc[i]*4;
                int c = kg >> 8, rem = kg & 255;
                int dy = rem >> 4, dx = rem & 15;
                ga = abase[i] + (size_t)c*(IMGW*IMGW) + dy*IMGW + dx;
            } else {
                ga = abase[i] + k0;
            }
            cp_async16(&As[buf*4608 + lrow[i]*36 + lkc[i]*4], ga);
            cp_async16(&Bs[buf*4608 + lrow[i]*36 + lkc[i]*4], bbase[i] + k0);
        }
    };

    float acc[4][4][4] = {};

    load_tiles(0, 0);
    CP_COMMIT();
    const int nk = K / 32;
    for (int t = 0; t < nk; t++) {
        int buf = t & 1;
        if (t + 1 < nk) load_tiles(buf ^ 1, (t+1)*32);
        CP_COMMIT();
        CP_WAIT(1);
        __syncthreads();

        const float* Ab = &As[buf*4608];
        const float* Bb = &Bs[buf*4608];
        #pragma unroll
        for (int ks = 0; ks < 4; ks++) {
            int k = ks * 8;
            uint32_t af[4][4], bf[4][2];
            #pragma unroll
            for (int i = 0; i < 4; i++) {
                int r = wm*64 + i*16 + g;
                af[i][0] = f2tf(Ab[(r  )*36 + k + tig]);
                af[i][1] = f2tf(Ab[(r+8)*36 + k + tig]);
                af[i][2] = f2tf(Ab[(r  )*36 + k + tig + 4]);
                af[i][3] = f2tf(Ab[(r+8)*36 + k + tig + 4]);
            }
            #pragma unroll
            for (int j = 0; j < 4; j++) {
                int n = wn*32 + j*8 + g;
                bf[j][0] = f2tf(Bb[n*36 + k + tig]);
                bf[j][1] = f2tf(Bb[n*36 + k + tig + 4]);
            }
            #pragma unroll
            for (int i = 0; i < 4; i++)
                #pragma unroll
                for (int j = 0; j < 4; j++)
                    mma_tf32(acc[i][j], af[i], bf[j][0], bf[j][1]);
        }
        __syncthreads();
    }

    float* C = CONV ? g_h : Cout;
    #pragma unroll
    for (int i = 0; i < 4; i++) {
        int r = m0 + wm*64 + i*16 + g;
        #pragma unroll
        for (int j = 0; j < 4; j++) {
            int cc = n0 + wn*32 + j*8 + tig*2;
            float2 v0 = make_float2(acc[i][j][0] + bias[cc], acc[i][j][1] + bias[cc+1]);
            float2 v1 = make_float2(acc[i][j][2] + bias[cc], acc[i][j][3] + bias[cc+1]);
            *(float2*)&C[(size_t)r*512 + cc] = v0;
            *(float2*)&C[(size_t)(r+8)*512 + cc] = v1;
        }
    }
}

// =================================================================
// Flash attention, tf32 MMA, fused Q-proj, N-split warps.
//   OCCUPANCY build: Q persists in smem (no aq regs), single KV
//   buffer, P in its own region -> 72.2 KB smem, <=112 regs,
//   3 CTAs/SM (28% occ vs 18%).
//   Strides: Qs/Ps 68 (column-pattern loads clean), KV 72
//   (PV row-pattern loads clean; S-phase 2-way accepted).
// =================================================================
#define A68 68
#define A72 72
// Qs 96x68 | KV 64x72 | Ps 96x68 | Msm 96x2 | Ssm 96x2
#define ATTN_SMEM ((96*A68 + 64*A72 + 96*A68 + 96*2 + 96*2)*4)   // 72192 B

__global__ __launch_bounds__(192, 3) void attn_mma() {
    extern __shared__ float sm[];
    float* Qs  = sm;                     // [96][68]: H -> Q bits (persistent)
    float* KVs = sm + 96*A68;            // [64][72] single buffer
    float* Ps  = KVs + 64*A72;           // [96][68]: G (prologue) -> P bits
    float* Msm = Ps + 96*A68;            // [96][2]
    float* Ssm = Msm + 96*2;             // [96][2]
    uint32_t* Qb = (uint32_t*)Qs;
    uint32_t* Pb = (uint32_t*)Ps;

    const int qt = blockIdx.x, hh = blockIdx.y, b = blockIdx.z;
    const int tid = threadIdx.x;
    const int w = tid >> 5, lane = tid & 31;
    const int wm = w >> 1, wn = w & 1;
    const int g = lane >> 2, tig = lane & 3;
    const size_t rowbase = (size_t)(b*SLEN)*EMB_ + hh*HD;
    const int rr[2] = { wm*32 + g, wm*32 + 16 + g };

    auto loadKV = [&](int kt) {
        const float* kb = g_h + rowbase + (size_t)(kt*64)*EMB_;
        for (int v = tid; v < 64*16; v += 192) {
            int r = v >> 4, cq = (v & 15) * 4;
            cp_async16(&KVs[r*A72 + cq], kb + (size_t)r*EMB_ + cq);
        }
    };

    // ---- prologue loads: KV tile 0, H -> Qs, G -> Ps ----
    loadKV(0);
    {
        const float* hb = g_h + rowbase + (size_t)(qt*96)*EMB_;
        for (int v = tid; v < 96*16; v += 192) {
            int r = v >> 4, cq = (v & 15) * 4;
            cp_async16(&Qs[r*A68 + cq], hb + (size_t)r*EMB_ + cq);
        }
        for (int v = tid; v < 64*16; v += 192) {
            int r = v >> 4, cq = (v & 15) * 4;
            cp_async16(&Ps[r*A68 + cq], g_Gt + r*64 + cq);
        }
    }
    CP_COMMIT();
    CP_WAIT(0);
    __syncthreads();

    // ---- Q = H @ G (warp: 32 rows x 32 cols), Q bits -> Qs ----
    {
        float qc[2][4][4] = {};
        #pragma unroll
        for (int ks = 0; ks < 8; ks++) {
            int k = ks*8;
            uint32_t ha[2][4];
            #pragma unroll
            for (int i = 0; i < 2; i++) {
                ha[i][0] = f2tf(Qs[(rr[i]  )*A68 + k + tig]);
                ha[i][1] = f2tf(Qs[(rr[i]+8)*A68 + k + tig]);
                ha[i][2] = f2tf(Qs[(rr[i]  )*A68 + k + tig + 4]);
                ha[i][3] = f2tf(Qs[(rr[i]+8)*A68 + k + tig + 4]);
            }
            #pragma unroll
            for (int j = 0; j < 4; j++) {
                int n = wn*32 + j*8 + g;
                uint32_t b0 = f2tf(Ps[n*A68 + k + tig]);
                uint32_t b1 = f2tf(Ps[n*A68 + k + tig + 4]);
                mma_tf32(qc[0][j], ha[0], b0, b1);
                mma_tf32(qc[1][j], ha[1], b0, b1);
            }
        }
        __syncthreads();   // everyone done reading H (Qs) and G (Ps)
        #pragma unroll
        for (int i = 0; i < 2; i++)
            #pragma unroll
            for (int j = 0; j < 4; j++) {
                int cc = wn*32 + j*8 + tig*2;
                *(uint2*)&Qb[(rr[i]  )*A68 + cc] = make_uint2(f2tf(qc[i][j][0]), f2tf(qc[i][j][1]));
                *(uint2*)&Qb[(rr[i]+8)*A68 + cc] = make_uint2(f2tf(qc[i][j][2]), f2tf(qc[i][j][3]));
            }
        __syncthreads();   // full-width Q bits visible to all warps
    }

    float oacc[2][4][4] = {};
    float m_[2][2], l_[2][2];
    #pragma unroll
    for (int i = 0; i < 2; i++) { m_[i][0] = m_[i][1] = -3.0e38f; l_[i][0] = l_[i][1] = 0.f; }

    for (int kt = 0; kt < 9; kt++) {
        if (kt > 0) {                     // wait for load issued at end of prev iter
            CP_WAIT(0);
            __syncthreads();
        }

        // ---- convert KV to tf32 bits in place (clean float4) ----
        {
            uint32_t* U = (uint32_t*)KVs;
            for (int v = tid; v < 64*16; v += 192) {
                int r = v >> 4, c = (v & 15) * 4;
                float4 f = *(float4*)&KVs[r*A72 + c];
                uint4 u;
                u.x = f2tf(f.x); u.y = f2tf(f.y); u.z = f2tf(f.z); u.w = f2tf(f.w);
                *(uint4*)&U[r*A72 + c] = u;
            }
        }
        __syncthreads();
        const uint32_t* KB = (const uint32_t*)KVs;

        // ---- S = Q K^T (Q frags reloaded from Qs: clean column loads) ----
        float sacc[2][4][4] = {};
        #pragma unroll
        for (int ks = 0; ks < 8; ks++) {
            int k = ks*8;
            uint32_t a0[4], a1[4];
            a0[0] = Qb[(rr[0]  )*A68 + k + tig];
            a0[1] = Qb[(rr[0]+8)*A68 + k + tig];
            a0[2] = Qb[(rr[0]  )*A68 + k + tig + 4];
            a0[3] = Qb[(rr[0]+8)*A68 + k + tig + 4];
            a1[0] = Qb[(rr[1]  )*A68 + k + tig];
            a1[1] = Qb[(rr[1]+8)*A68 + k + tig];
            a1[2] = Qb[(rr[1]  )*A68 + k + tig + 4];
            a1[3] = Qb[(rr[1]+8)*A68 + k + tig + 4];
            #pragma unroll
            for (int j = 0; j < 4; j++) {
                int l = wn*32 + j*8 + g;
                uint32_t b0 = KB[l*A72 + k + tig];
                uint32_t b1 = KB[l*A72 + k + tig + 4];
                mma_tf32(sacc[0][j], a0, b0, b1);
                mma_tf32(sacc[1][j], a1, b0, b1);
            }
        }

        // ---- partial row max, quad-reduce, exchange across wn pair ----
        float pm[2][2];
        #pragma unroll
        for (int i = 0; i < 2; i++) {
            pm[i][0] = fmaxf(fmaxf(sacc[i][0][0], sacc[i][0][1]), fmaxf(sacc[i][1][0], sacc[i][1][1]));
            pm[i][0] = fmaxf(pm[i][0], fmaxf(fmaxf(sacc[i][2][0], sacc[i][2][1]), fmaxf(sacc[i][3][0], sacc[i][3][1])));
            pm[i][1] = fmaxf(fmaxf(sacc[i][0][2], sacc[i][0][3]), fmaxf(sacc[i][1][2], sacc[i][1][3]));
            pm[i][1] = fmaxf(pm[i][1], fmaxf(fmaxf(sacc[i][2][2], sacc[i][2][3]), fmaxf(sacc[i][3][2], sacc[i][3][3])));
            #pragma unroll
            for (int r = 0; r < 2; r++) {
                pm[i][r] = fmaxf(pm[i][r], __shfl_xor_sync(0xffffffffu, pm[i][r], 1));
                pm[i][r] = fmaxf(pm[i][r], __shfl_xor_sync(0xffffffffu, pm[i][r], 2));
            }
        }
        if (tig == 0) {
            #pragma unroll
            for (int i = 0; i < 2; i++) {
                Msm[(rr[i]  )*2 + wn] = pm[i][0];
                Msm[(rr[i]+8)*2 + wn] = pm[i][1];
            }
        }
        __syncthreads();

        float alpha[2][2];
        #pragma unroll
        for (int i = 0; i < 2; i++) {
            #pragma unroll
            for (int r = 0; r < 2; r++) {
                int row = rr[i] + r*8;
                float mt = fmaxf(Msm[row*2], Msm[row*2 + 1]);
                float mnew = fmaxf(m_[i][r], mt);
                alpha[i][r] = __expf(m_[i][r] - mnew);
                m_[i][r] = mnew;
            }
        }

        // ---- p = exp(s-m) -> Ps, partial sums, exchange ----
        float psum[2][2] = {};
        #pragma unroll
        for (int i = 0; i < 2; i++)
            #pragma unroll
            for (int j = 0; j < 4; j++) {
                int cc = wn*32 + j*8 + tig*2;
                float p0 = __expf(sacc[i][j][0] - m_[i][0]);
                float p1 = __expf(sacc[i][j][1] - m_[i][0]);
                float p2 = __expf(sacc[i][j][2] - m_[i][1]);
                float p3 = __expf(sacc[i][j][3] - m_[i][1]);
                psum[i][0] += p0 + p1;
                psum[i][1] += p2 + p3;
                *(uint2*)&Pb[(rr[i]  )*A68 + cc] = make_uint2(f2tf(p0), f2tf(p1));
                *(uint2*)&Pb[(rr[i]+8)*A68 + cc] = make_uint2(f2tf(p2), f2tf(p3));
            }
        #pragma unroll
        for (int i = 0; i < 2; i++)
            #pragma unroll
            for (int r = 0; r < 2; r++) {
                psum[i][r] += __shfl_xor_sync(0xffffffffu, psum[i][r], 1);
                psum[i][r] += __shfl_xor_sync(0xffffffffu, psum[i][r], 2);
            }
        if (tig == 0) {
            #pragma unroll
            for (int i = 0; i < 2; i++) {
                Ssm[(rr[i]  )*2 + wn] = psum[i][0];
                Ssm[(rr[i]+8)*2 + wn] = psum[i][1];
            }
        }
        __syncthreads();   // P full width + sums visible

        #pragma unroll
        for (int i = 0; i < 2; i++) {
            #pragma unroll
            for (int r = 0; r < 2; r++) {
                int row = rr[i] + r*8;
                l_[i][r] = l_[i][r]*alpha[i][r] + Ssm[row*2] + Ssm[row*2 + 1];
            }
            #pragma unroll
            for (int j = 0; j < 4; j++) {
                oacc[i][j][0] *= alpha[i][0]; oacc[i][j][1] *= alpha[i][0];
                oacc[i][j][2] *= alpha[i][1]; oacc[i][j][3] *= alpha[i][1];
            }
        }

        // ---- O += P V  (P column loads clean @68; V row loads clean @72) ----
        #pragma unroll
        for (int ks = 0; ks < 8; ks++) {
            int k = ks*8;
            uint32_t ap[2][4];
            #pragma unroll
            for (int i = 0; i < 2; i++) {
                ap[i][0] = Pb[(rr[i]  )*A68 + k + tig];
                ap[i][1] = Pb[(rr[i]+8)*A68 + k + tig];
                ap[i][2] = Pb[(rr[i]  )*A68 + k + tig + 4];
                ap[i][3] = Pb[(rr[i]+8)*A68 + k + tig + 4];
            }
            #pragma unroll
            for (int j = 0; j < 4; j++) {
                int d = wn*32 + j*8 + g;
                uint32_t b0 = KB[(k + tig    )*A72 + d];
                uint32_t b1 = KB[(k + tig + 4)*A72 + d];
                mma_tf32(oacc[0][j], ap[0], b0, b1);
                mma_tf32(oacc[1][j], ap[1], b0, b1);
            }
        }

        // ---- issue next KV load (single buffer: must sync first) ----
        if (kt < 8) {
            __syncthreads();           // all warps done reading KVs
            loadKV(kt + 1);
            CP_COMMIT();
        }
    }

    // ---- epilogue ----
    float* ob = g_ctx + rowbase + (size_t)(qt*96)*EMB_;
    #pragma unroll
    for (int i = 0; i < 2; i++)
        #pragma unroll
        for (int r = 0; r < 2; r++) {
            int row = rr[i] + r*8;
            float inv = 1.0f / l_[i][r];
            #pragma unroll
            for (int j = 0; j < 4; j++) {
                int d = wn*32 + j*8 + tig*2;
                float2 v = make_float2(oacc[i][j][r*2]*inv, oacc[i][j][r*2+1]*inv);
                *(float2*)&ob[(size_t)row*EMB_ + d] = v;
            }
        }
}

// =================================================================
extern "C" void kernel_launch(void* const* d_in, const int* in_sizes, int n_in,
                              void* d_out, int out_size) {
    (void)in_sizes; (void)n_in; (void)out_size;
    const float* x      = (const float*)d_in[0];
    const float* conv_w = (const float*)d_in[1];
    const float* conv_b = (const float*)d_in[2];
    const float* wq     = (const float*)d_in[3];
    const float* wk     = (const float*)d_in[4];
    const float* wv     = (const float*)d_in[5];
    const float* wo     = (const float*)d_in[6];
    const float* bo     = (const float*)d_in[7];
    float* out = (float*)d_out;

    cudaFuncSetAttribute(mma_gemm<true>,  cudaFuncAttributeMaxDynamicSharedMemorySize, GEMM_SMEM);
    cudaFuncSetAttribute(mma_gemm<false>, cudaFuncAttributeMaxDynamicSharedMemorySize, GEMM_SMEM);
    cudaFuncSetAttribute(attn_mma, cudaFuncAttributeMaxDynamicSharedMemorySize, ATTN_SMEM);

    prep_G  <<<64, 64>>>(wq, wk);
    prep_Wvo<<<512, 512>>>(wv, wo);
    mma_gemm<true><<<dim3(4, 144), 256, GEMM_SMEM>>>(x, conv_w, conv_b, nullptr, KCONV);
    attn_mma<<<dim3(6, NHEAD, BATCH), 192, ATTN_SMEM>>>();
    mma_gemm<false><<<dim3(4, 144), 256, GEMM_SMEM>>>(nullptr, nullptr, bo, out, EMB_);
}

// round 11
// speedup vs baseline: 1.5318x; 1.4685x over previous
#include <cuda_runtime.h>
#include <cuda_fp16.h>
#include <math.h>
#include <stdint.h>

// Shapes
#define BATCH   32
#define SLEN    576
#define EMB_    512
#define NHEAD   8
#define HD      64
#define TOK     (BATCH*SLEN) // 18432
#define IMGW    384
#define KCONV   768

// -------- scratch (device globals) --------
__device__ __half g_hh  [TOK*EMB_];   // patch embeddings (fp16)
__device__ __half g_ctxh[TOK*EMB_];   // att @ h (fp16)
__device__ __half g_Gh  [HD*HD];      // folded Wq^T Wk * 0.125 (fp16)
__device__ __half g_WvoTh[EMB_*EMB_]; // folded Wv->Wo (fp16)

// ---------------- helpers ----------------
__device__ __forceinline__ uint32_t f2tf(float x) {
    uint32_t r; asm("cvt.rna.tf32.f32 %0, %1;" : "=r"(r) : "f"(x)); return r;
}
__device__ __forceinline__ uint32_t pack2(float a, float b) {
    __half2 h = __floats2half2_rn(a, b);
    return *(uint32_t*)&h;
}
__device__ __forceinline__ void mma_tf32(float* c, const uint32_t* a, uint32_t b0, uint32_t b1) {
    asm volatile(
        "mma.sync.aligned.m16n8k8.row.col.f32.tf32.tf32.f32 "
        "{%0,%1,%2,%3}, {%4,%5,%6,%7}, {%8,%9}, {%0,%1,%2,%3};\n"
        : "+f"(c[0]), "+f"(c[1]), "+f"(c[2]), "+f"(c[3])
        : "r"(a[0]), "r"(a[1]), "r"(a[2]), "r"(a[3]), "r"(b0), "r"(b1));
}
__device__ __forceinline__ void mma_f16(float* c, const uint32_t* a, uint32_t b0, uint32_t b1) {
    asm volatile(
        "mma.sync.aligned.m16n8k16.row.col.f32.f16.f16.f32 "
        "{%0,%1,%2,%3}, {%4,%5,%6,%7}, {%8,%9}, {%0,%1,%2,%3};\n"
        : "+f"(c[0]), "+f"(c[1]), "+f"(c[2]), "+f"(c[3])
        : "r"(a[0]), "r"(a[1]), "r"(a[2]), "r"(a[3]), "r"(b0), "r"(b1));
}
__device__ __forceinline__ void ldsm_x4_trans(uint32_t& r0, uint32_t& r1, uint32_t& r2, uint32_t& r3,
                                              uint32_t addr) {
    asm volatile("ldmatrix.sync.aligned.m8n8.x4.trans.shared.b16 {%0,%1,%2,%3}, [%4];"
        : "=r"(r0), "=r"(r1), "=r"(r2), "=r"(r3) : "r"(addr));
}
__device__ __forceinline__ void cp_async16(void* smem, const void* gmem) {
    uint32_t s = (uint32_t)__cvta_generic_to_shared(smem);
    asm volatile("cp.async.cg.shared.global [%0], [%1], 16;\n" :: "r"(s), "l"(gmem));
}
#define CP_COMMIT() asm volatile("cp.async.commit_group;\n")
#define CP_WAIT(n)  asm volatile("cp.async.wait_group %0;\n" :: "n"(n))

// =================================================================
// Weight folding preps (tiny) -> fp16 outputs
// =================================================================
__global__ void prep_G(const float* __restrict__ wq, const float* __restrict__ wk) {
    int dp = blockIdx.x, d = threadIdx.x;
    float s = 0.f;
    #pragma unroll 8
    for (int e = 0; e < 64; e++) s += wq[e*64 + d] * wk[e*64 + dp];
    g_Gh[dp*64 + d] = __float2half(0.125f * s);
}
__global__ void prep_Wvo(const float* __restrict__ wv, const float* __restrict__ wo) {
    int f = blockIdx.x, hd = threadIdx.x;
    int h = hd >> 6, d = hd & 63;
    float s = 0.f;
    #pragma unroll 8
    for (int e = 0; e < 64; e++) s += wv[e*64 + d] * wo[(size_t)f*512 + h*64 + e];
    g_WvoTh[(size_t)f*512 + hd] = __float2half(s);
}

// =================================================================
// Conv patch-embed GEMM (tf32 math, fp16 output to g_hh)
//   M=18432, N=512, K=768.  BM=BN=128 BK=32, 8 warps.
// =================================================================
#define GEMM_SMEM (2*128*36*2*4)   // 73728 B

__global__ __launch_bounds__(256) void conv_gemm(const float* __restrict__ x,
                                                 const float* __restrict__ w,
                                                 const float* __restrict__ bias) {
    extern __shared__ float sm[];
    float* As = sm;
    float* Bs = sm + 2*128*36;

    const int tid = threadIdx.x;
    const int lane = tid & 31;
    const int wr = tid >> 5, wm = wr & 1, wn = wr >> 1;
    const int g = lane >> 2, tig = lane & 3;
    const int m0 = blockIdx.y * 128, n0 = blockIdx.x * 128;

    int lrow[4], lkc[4];
    const float* abase[4];
    const float* bbase[4];
    #pragma unroll
    for (int i = 0; i < 4; i++) {
        int v = tid + i*256;
        int row = v >> 3, kc = v & 7;
        lrow[i] = row; lkc[i] = kc;
        int m = m0 + row;
        int bb = m / 576, p = m % 576;
        int py = p / 24, px = p % 24;
        abase[i] = x + (size_t)bb*3*IMGW*IMGW + (size_t)(py*16)*IMGW + px*16;
        bbase[i] = w + (size_t)(n0 + row)*KCONV + kc*4;
    }

    auto load_tiles = [&](int buf, int k0) {
        #pragma unroll
        for (int i = 0; i < 4; i++) {
            int kg = k0 + lkc[i]*4;
            int c = kg >> 8, rem = kg & 255;
            int dy = rem >> 4, dx = rem & 15;
            const float* ga = abase[i] + (size_t)c*(IMGW*IMGW) + dy*IMGW + dx;
            cp_async16(&As[buf*4608 + lrow[i]*36 + lkc[i]*4], ga);
            cp_async16(&Bs[buf*4608 + lrow[i]*36 + lkc[i]*4], bbase[i] + k0);
        }
    };

    float acc[4][4][4] = {};

    load_tiles(0, 0);
    CP_COMMIT();
    const int nk = KCONV / 32;
    for (int t = 0; t < nk; t++) {
        int buf = t & 1;
        if (t + 1 < nk) load_tiles(buf ^ 1, (t+1)*32);
        CP_COMMIT();
        CP_WAIT(1);
        __syncthreads();

        const float* Ab = &As[buf*4608];
        const float* Bb = &Bs[buf*4608];
        #pragma unroll
        for (int ks = 0; ks < 4; ks++) {
            int k = ks * 8;
            uint32_t af[4][4], bf[4][2];
            #pragma unroll
            for (int i = 0; i < 4; i++) {
                int r = wm*64 + i*16 + g;
                af[i][0] = f2tf(Ab[(r  )*36 + k + tig]);
                af[i][1] = f2tf(Ab[(r+8)*36 + k + tig]);
                af[i][2] = f2tf(Ab[(r  )*36 + k + tig + 4]);
                af[i][3] = f2tf(Ab[(r+8)*36 + k + tig + 4]);
            }
            #pragma unroll
            for (int j = 0; j < 4; j++) {
                int n = wn*32 + j*8 + g;
                bf[j][0] = f2tf(Bb[n*36 + k + tig]);
                bf[j][1] = f2tf(Bb[n*36 + k + tig + 4]);
            }
            #pragma unroll
            for (int i = 0; i < 4; i++)
                #pragma unroll
                for (int j = 0; j < 4; j++)
                    mma_tf32(acc[i][j], af[i], bf[j][0], bf[j][1]);
        }
        __syncthreads();
    }

    #pragma unroll
    for (int i = 0; i < 4; i++) {
        int r = m0 + wm*64 + i*16 + g;
        #pragma unroll
        for (int j = 0; j < 4; j++) {
            int cc = n0 + wn*32 + j*8 + tig*2;
            float b0 = bias[cc], b1 = bias[cc+1];
            *(__half2*)&g_hh[(size_t)r*512 + cc]     = __floats2half2_rn(acc[i][j][0] + b0, acc[i][j][1] + b1);
            *(__half2*)&g_hh[(size_t)(r+8)*512 + cc] = __floats2half2_rn(acc[i][j][2] + b0, acc[i][j][3] + b1);
        }
    }
}

// =================================================================
// Flash attention, fp16 m16n8k16, fused Q-proj, N-split warps.
//   Word layout (uint32 = half2 packed along k):
//     Qw [96][36] : H -> Q ;  KV [2][64][36] ;  Pw [96][36]
//   S-phase: direct clean loads; PV B via ldmatrix.x4.trans.
// =================================================================
#define AWS 36
#define KV_OFF   (96*AWS)             // 3456
#define PS_OFF   (KV_OFF + 2*64*AWS)  // 8064
#define MS_OFF   (PS_OFF + 96*AWS)    // 11520
#define SS_OFF   (MS_OFF + 192)       // 11712
#define ATTN_SMEM ((SS_OFF + 192)*4)  // 47616 B

__global__ __launch_bounds__(192, 3) void attn_f16() {
    extern __shared__ float sm[];
    uint32_t* QW = (uint32_t*)sm;
    uint32_t* KVW = QW + KV_OFF;
    uint32_t* PW = QW + PS_OFF;
    float* Msm = sm + MS_OFF;
    float* Ssm = sm + SS_OFF;

    const int qt = blockIdx.x, hh = blockIdx.y, b = blockIdx.z;
    const int tid = threadIdx.x;
    const int wr = tid >> 5, lane = tid & 31;
    const int wm = wr >> 1, wn = wr & 1;
    const int g = lane >> 2, tig = lane & 3;
    const size_t rowbase = (size_t)(b*SLEN)*EMB_ + hh*HD;   // in halves
    const int rr[2] = { wm*32 + g, wm*32 + 16 + g };

    // ldmatrix per-lane constants
    const int lm_row  = lane & 15;
    const int lm_colw = ((lane >> 4) & 1) * 4 + wn*16;

    auto loadKV = [&](int buf, int kt) {
        const __half* kb = g_hh + rowbase + (size_t)(kt*64)*EMB_;
        for (int v = tid; v < 512; v += 192) {
            int r = v >> 3, c8 = (v & 7);
            cp_async16(&KVW[buf*64*AWS + r*AWS + c8*4], kb + (size_t)r*EMB_ + c8*8);
        }
    };

    // ---- prologue: KV tile 0 -> buf0, H -> QW, G -> PW ----
    loadKV(0, 0);
    {
        const __half* hb = g_hh + rowbase + (size_t)(qt*96)*EMB_;
        for (int v = tid; v < 768; v += 192) {
            int r = v >> 3, c8 = (v & 7);
            cp_async16(&QW[r*AWS + c8*4], hb + (size_t)r*EMB_ + c8*8);
        }
        for (int v = tid; v < 512; v += 192) {
            int r = v >> 3, c8 = (v & 7);
            cp_async16(&PW[r*AWS + c8*4], g_Gh + r*64 + c8*8);
        }
    }
    CP_COMMIT();
    CP_WAIT(0);
    __syncthreads();

    // ---- Q = H @ G  (fp16 mma; H in QW, G in PW) ----
    {
        float qc[2][4][4] = {};
        #pragma unroll
        for (int ks = 0; ks < 4; ks++) {
            int w0 = ks*8;
            uint32_t ha[2][4];
            #pragma unroll
            for (int i = 0; i < 2; i++) {
                ha[i][0] = QW[(rr[i]  )*AWS + w0 + tig];
                ha[i][1] = QW[(rr[i]+8)*AWS + w0 + tig];
                ha[i][2] = QW[(rr[i]  )*AWS + w0 + tig + 4];
                ha[i][3] = QW[(rr[i]+8)*AWS + w0 + tig + 4];
            }
            #pragma unroll
            for (int j = 0; j < 4; j++) {
                int n = wn*32 + j*8 + g;
                uint32_t b0 = PW[n*AWS + w0 + tig];
                uint32_t b1 = PW[n*AWS + w0 + tig + 4];
                mma_f16(qc[0][j], ha[0], b0, b1);
                mma_f16(qc[1][j], ha[1], b0, b1);
            }
        }
        __syncthreads();   // everyone done reading H (QW) and G (PW)
        #pragma unroll
        for (int i = 0; i < 2; i++)
            #pragma unroll
            for (int j = 0; j < 4; j++) {
                int cw = wn*16 + j*4 + tig;
                QW[(rr[i]  )*AWS + cw] = pack2(qc[i][j][0], qc[i][j][1]);
                QW[(rr[i]+8)*AWS + cw] = pack2(qc[i][j][2], qc[i][j][3]);
            }
        __syncthreads();   // full-width Q visible
    }

    float oacc[2][4][4] = {};
    float m_[2][2], l_[2][2];
    #pragma unroll
    for (int i = 0; i < 2; i++) { m_[i][0] = m_[i][1] = -3.0e38f; l_[i][0] = l_[i][1] = 0.f; }

    const uint32_t kv_base_addr = (uint32_t)__cvta_generic_to_shared(KVW);

    for (int kt = 0; kt < 9; kt++) {
        int buf = kt & 1;
        CP_WAIT(0);
        __syncthreads();                      // KV[buf] ready; buf^1 readers done

        if (kt + 1 < 9) { loadKV(buf ^ 1, kt + 1); CP_COMMIT(); }

        const uint32_t* KB = KVW + buf*64*AWS;
        const uint32_t kaddr = kv_base_addr + (buf*64*AWS)*4;

        // ---- S = Q K^T ----
        float sacc[2][4][4] = {};
        #pragma unroll
        for (int ks = 0; ks < 4; ks++) {
            int w0 = ks*8;
            uint32_t a0[4], a1[4];
            a0[0] = QW[(rr[0]  )*AWS + w0 + tig];
            a0[1] = QW[(rr[0]+8)*AWS + w0 + tig];
            a0[2] = QW[(rr[0]  )*AWS + w0 + tig + 4];
            a0[3] = QW[(rr[0]+8)*AWS + w0 + tig + 4];
            a1[0] = QW[(rr[1]  )*AWS + w0 + tig];
            a1[1] = QW[(rr[1]+8)*AWS + w0 + tig];
            a1[2] = QW[(rr[1]  )*AWS + w0 + tig + 4];
            a1[3] = QW[(rr[1]+8)*AWS + w0 + tig + 4];
            #pragma unroll
            for (int j = 0; j < 4; j++) {
                int l = wn*32 + j*8 + g;
                uint32_t b0 = KB[l*AWS + w0 + tig];
                uint32_t b1 = KB[l*AWS + w0 + tig + 4];
                mma_f16(sacc[0][j], a0, b0, b1);
                mma_f16(sacc[1][j], a1, b0, b1);
            }
        }

        // ---- partial row max, quad-reduce, exchange across wn pair ----
        float pm[2][2];
        #pragma unroll
        for (int i = 0; i < 2; i++) {
            pm[i][0] = fmaxf(fmaxf(sacc[i][0][0], sacc[i][0][1]), fmaxf(sacc[i][1][0], sacc[i][1][1]));
            pm[i][0] = fmaxf(pm[i][0], fmaxf(fmaxf(sacc[i][2][0], sacc[i][2][1]), fmaxf(sacc[i][3][0], sacc[i][3][1])));
            pm[i][1] = fmaxf(fmaxf(sacc[i][0][2], sacc[i][0][3]), fmaxf(sacc[i][1][2], sacc[i][1][3]));
            pm[i][1] = fmaxf(pm[i][1], fmaxf(fmaxf(sacc[i][2][2], sacc[i][2][3]), fmaxf(sacc[i][3][2], sacc[i][3][3])));
            #pragma unroll
            for (int r = 0; r < 2; r++) {
                pm[i][r] = fmaxf(pm[i][r], __shfl_xor_sync(0xffffffffu, pm[i][r], 1));
                pm[i][r] = fmaxf(pm[i][r], __shfl_xor_sync(0xffffffffu, pm[i][r], 2));
            }
        }
        if (tig == 0) {
            #pragma unroll
            for (int i = 0; i < 2; i++) {
                Msm[(rr[i]  )*2 + wn] = pm[i][0];
                Msm[(rr[i]+8)*2 + wn] = pm[i][1];
            }
        }
        __syncthreads();

        float alpha[2][2];
        #pragma unroll
        for (int i = 0; i < 2; i++) {
            #pragma unroll
            for (int r = 0; r < 2; r++) {
                int row = rr[i] + r*8;
                float mt = fmaxf(Msm[row*2], Msm[row*2 + 1]);
                float mnew = fmaxf(m_[i][r], mt);
                alpha[i][r] = __expf(m_[i][r] - mnew);
                m_[i][r] = mnew;
            }
        }

        // ---- p = exp(s-m) -> PW (half2), partial sums, exchange ----
        float psum[2][2] = {};
        #pragma unroll
        for (int i = 0; i < 2; i++)
            #pragma unroll
            for (int j = 0; j < 4; j++) {
                int cw = wn*16 + j*4 + tig;
                float p0 = __expf(sacc[i][j][0] - m_[i][0]);
                float p1 = __expf(sacc[i][j][1] - m_[i][0]);
                float p2 = __expf(sacc[i][j][2] - m_[i][1]);
                float p3 = __expf(sacc[i][j][3] - m_[i][1]);
                psum[i][0] += p0 + p1;
                psum[i][1] += p2 + p3;
                PW[(rr[i]  )*AWS + cw] = pack2(p0, p1);
                PW[(rr[i]+8)*AWS + cw] = pack2(p2, p3);
            }
        #pragma unroll
        for (int i = 0; i < 2; i++)
            #pragma unroll
            for (int r = 0; r < 2; r++) {
                psum[i][r] += __shfl_xor_sync(0xffffffffu, psum[i][r], 1);
                psum[i][r] += __shfl_xor_sync(0xffffffffu, psum[i][r], 2);
            }
        if (tig == 0) {
            #pragma unroll
            for (int i = 0; i < 2; i++) {
                Ssm[(rr[i]  )*2 + wn] = psum[i][0];
                Ssm[(rr[i]+8)*2 + wn] = psum[i][1];
            }
        }
        __syncthreads();   // P full width + sums visible

        #pragma unroll
        for (int i = 0; i < 2; i++) {
            #pragma unroll
            for (int r = 0; r < 2; r++) {
                int row = rr[i] + r*8;
                l_[i][r] = l_[i][r]*alpha[i][r] + Ssm[row*2] + Ssm[row*2 + 1];
            }
            #pragma unroll
            for (int j = 0; j < 4; j++) {
                oacc[i][j][0] *= alpha[i][0]; oacc[i][j][1] *= alpha[i][0];
                oacc[i][j][2] *= alpha[i][1]; oacc[i][j][3] *= alpha[i][1];
            }
        }

        // ---- O += P V  (A = P direct; B via ldmatrix.x4.trans of KV) ----
        #pragma unroll
        for (int ks = 0; ks < 4; ks++) {
            int w0 = ks*8;
            uint32_t ap[2][4];
            #pragma unroll
            for (int i = 0; i < 2; i++) {
                ap[i][0] = PW[(rr[i]  )*AWS + w0 + tig];
                ap[i][1] = PW[(rr[i]+8)*AWS + w0 + tig];
                ap[i][2] = PW[(rr[i]  )*AWS + w0 + tig + 4];
                ap[i][3] = PW[(rr[i]+8)*AWS + w0 + tig + 4];
            }
            #pragma unroll
            for (int jp = 0; jp < 2; jp++) {
                uint32_t r0, r1, r2, r3;
                uint32_t addr = kaddr + ((ks*16 + lm_row)*AWS + lm_colw + jp*8)*4;
                ldsm_x4_trans(r0, r1, r2, r3, addr);
                mma_f16(oacc[0][jp*2    ], ap[0], r0, r1);
                mma_f16(oacc[1][jp*2    ], ap[1], r0, r1);
                mma_f16(oacc[0][jp*2 + 1], ap[0], r2, r3);
                mma_f16(oacc[1][jp*2 + 1], ap[1], r2, r3);
            }
        }
    }

    // ---- epilogue: g_ctx (fp16) ----
    __half* ob = g_ctxh + rowbase + (size_t)(qt*96)*EMB_;
    #pragma unroll
    for (int i = 0; i < 2; i++)
        #pragma unroll
        for (int r = 0; r < 2; r++) {
            int row = rr[i] + r*8;
            float inv = 1.0f / l_[i][r];
            #pragma unroll
            for (int j = 0; j < 4; j++) {
                int d = wn*32 + j*8 + tig*2;
                *(__half2*)&ob[(size_t)row*EMB_ + d] =
                    __floats2half2_rn(oacc[i][j][r*2]*inv, oacc[i][j][r*2+1]*inv);
            }
        }
}

// =================================================================
// Output projection, fp16 m16n8k16: out = ctx @ WvoT^T + bo (fp32 out)
//   M=18432, N=512, K=512.  BM=BN=128, BK=32, 8 warps.
// =================================================================
#define PWS 20
#define PROJ_SMEM (2*128*PWS*2*4)   // 40960 B

__global__ __launch_bounds__(256, 2) void proj_f16(const float* __restrict__ bias,
                                                   float* __restrict__ C) {
    extern __shared__ float sm[];
    uint32_t* AW = (uint32_t*)sm;
    uint32_t* BW = AW + 2*128*PWS;

    const int tid = threadIdx.x;
    const int lane = tid & 31;
    const int wr = tid >> 5, wm = wr & 1, wn = wr >> 1;
    const int g = lane >> 2, tig = lane & 3;
    const int m0 = blockIdx.y * 128, n0 = blockIdx.x * 128;

    auto load_tiles = [&](int buf, int t) {
        #pragma unroll
        for (int i = 0; i < 2; i++) {
            int v = tid + i*256;
            int row = v >> 2, kc = v & 3;
            cp_async16(&AW[buf*128*PWS + row*PWS + kc*4],
                       g_ctxh + (size_t)(m0 + row)*512 + t*32 + kc*8);
            cp_async16(&BW[buf*128*PWS + row*PWS + kc*4],
                       g_WvoTh + (size_t)(n0 + row)*512 + t*32 + kc*8);
        }
    };

    float acc[4][4][4] = {};

    load_tiles(0, 0);
    CP_COMMIT();
    const int nk = 16;
    for (int t = 0; t < nk; t++) {
        int buf = t & 1;
        if (t + 1 < nk) load_tiles(buf ^ 1, t+1);
        CP_COMMIT();
        CP_WAIT(1);
        __syncthreads();

        const uint32_t* Ab = AW + buf*128*PWS;
        const uint32_t* Bb = BW + buf*128*PWS;
        #pragma unroll
        for (int ks = 0; ks < 2; ks++) {
            int w0 = ks*8;
            uint32_t af[4][4], bf[4][2];
            #pragma unroll
            for (int i = 0; i < 4; i++) {
                int r = wm*64 + i*16 + g;
                af[i][0] = Ab[(r  )*PWS + w0 + tig];
                af[i][1] = Ab[(r+8)*PWS + w0 + tig];
                af[i][2] = Ab[(r  )*PWS + w0 + tig + 4];
                af[i][3] = Ab[(r+8)*PWS + w0 + tig + 4];
            }
            #pragma unroll
            for (int j = 0; j < 4; j++) {
                int n = wn*32 + j*8 + g;
                bf[j][0] = Bb[n*PWS + w0 + tig];
                bf[j][1] = Bb[n*PWS + w0 + tig + 4];
            }
            #pragma unroll
            for (int i = 0; i < 4; i++)
                #pragma unroll
                for (int j = 0; j < 4; j++)
                    mma_f16(acc[i][j], af[i], bf[j][0], bf[j][1]);
        }
        __syncthreads();
    }

    #pragma unroll
    for (int i = 0; i < 4; i++) {
        int r = m0 + wm*64 + i*16 + g;
        #pragma unroll
        for (int j = 0; j < 4; j++) {
            int cc = n0 + wn*32 + j*8 + tig*2;
            float2 v0 = make_float2(acc[i][j][0] + bias[cc], acc[i][j][1] + bias[cc+1]);
            float2 v1 = make_float2(acc[i][j][2] + bias[cc], acc[i][j][3] + bias[cc+1]);
            *(float2*)&C[(size_t)r*512 + cc] = v0;
            *(float2*)&C[(size_t)(r+8)*512 + cc] = v1;
        }
    }
}

// =================================================================
extern "C" void kernel_launch(void* const* d_in, const int* in_sizes, int n_in,
                              void* d_out, int out_size) {
    (void)in_sizes; (void)n_in; (void)out_size;
    const float* x      = (const float*)d_in[0];
    const float* conv_w = (const float*)d_in[1];
    const float* conv_b = (const float*)d_in[2];
    const float* wq     = (const float*)d_in[3];
    const float* wk     = (const float*)d_in[4];
    const float* wv     = (const float*)d_in[5];
    const float* wo     = (const float*)d_in[6];
    const float* bo     = (const float*)d_in[7];
    float* out = (float*)d_out;

    cudaFuncSetAttribute(conv_gemm, cudaFuncAttributeMaxDynamicSharedMemorySize, GEMM_SMEM);
    cudaFuncSetAttribute(attn_f16,  cudaFuncAttributeMaxDynamicSharedMemorySize, ATTN_SMEM);
    cudaFuncSetAttribute(proj_f16,  cudaFuncAttributeMaxDynamicSharedMemorySize, PROJ_SMEM);

    prep_G  <<<64, 64>>>(wq, wk);
    prep_Wvo<<<512, 512>>>(wv, wo);
    conv_gemm<<<dim3(4, 144), 256, GEMM_SMEM>>>(x, conv_w, conv_b);
    attn_f16<<<dim3(6, NHEAD, BATCH), 192, ATTN_SMEM>>>();
    proj_f16<<<dim3(4, 144), 256, PROJ_SMEM>>>(bo, out);
}

// round 12
// speedup vs baseline: 1.6901x; 1.1033x over previous
#include <cuda_runtime.h>
#include <cuda_fp16.h>
#include <math.h>
#include <stdint.h>

// Shapes
#define BATCH   32
#define SLEN    576
#define EMB_    512
#define NHEAD   8
#define HD      64
#define TOK     (BATCH*SLEN) // 18432
#define IMGW    384
#define KCONV   768
#define XELEM   (BATCH*3*IMGW*IMGW)   // 14155776

// -------- scratch (device globals) --------
__device__ __half g_xh  [XELEM];      // x in fp16
__device__ __half g_cwh [EMB_*KCONV]; // conv_w in fp16
__device__ __half g_hh  [TOK*EMB_];   // patch embeddings (fp16)
__device__ __half g_ctxh[TOK*EMB_];   // att @ h (fp16)
__device__ __half g_Gh  [HD*HD];      // folded Wq^T Wk * 0.125 (fp16)
__device__ __half g_WvoTh[EMB_*EMB_]; // folded Wv->Wo (fp16)

// ---------------- helpers ----------------
__device__ __forceinline__ uint32_t pack2(float a, float b) {
    __half2 h = __floats2half2_rn(a, b);
    return *(uint32_t*)&h;
}
__device__ __forceinline__ void mma_f16(float* c, const uint32_t* a, uint32_t b0, uint32_t b1) {
    asm volatile(
        "mma.sync.aligned.m16n8k16.row.col.f32.f16.f16.f32 "
        "{%0,%1,%2,%3}, {%4,%5,%6,%7}, {%8,%9}, {%0,%1,%2,%3};\n"
        : "+f"(c[0]), "+f"(c[1]), "+f"(c[2]), "+f"(c[3])
        : "r"(a[0]), "r"(a[1]), "r"(a[2]), "r"(a[3]), "r"(b0), "r"(b1));
}
__device__ __forceinline__ void ldsm_x4_trans(uint32_t& r0, uint32_t& r1, uint32_t& r2, uint32_t& r3,
                                              uint32_t addr) {
    asm volatile("ldmatrix.sync.aligned.m8n8.x4.trans.shared.b16 {%0,%1,%2,%3}, [%4];"
        : "=r"(r0), "=r"(r1), "=r"(r2), "=r"(r3) : "r"(addr));
}
__device__ __forceinline__ void cp_async16(void* smem, const void* gmem) {
    uint32_t s = (uint32_t)__cvta_generic_to_shared(smem);
    asm volatile("cp.async.cg.shared.global [%0], [%1], 16;\n" :: "r"(s), "l"(gmem));
}
#define CP_COMMIT() asm volatile("cp.async.commit_group;\n")
#define CP_WAIT(n)  asm volatile("cp.async.wait_group %0;\n" :: "n"(n))

// =================================================================
// Preps: fold weights; convert x and conv_w to fp16
// =================================================================
__global__ void prep_G(const float* __restrict__ wq, const float* __restrict__ wk) {
    int dp = blockIdx.x, d = threadIdx.x;
    float s = 0.f;
    #pragma unroll 8
    for (int e = 0; e < 64; e++) s += wq[e*64 + d] * wk[e*64 + dp];
    g_Gh[dp*64 + d] = __float2half(0.125f * s);
}
__global__ void prep_Wvo(const float* __restrict__ wv, const float* __restrict__ wo) {
    int f = blockIdx.x, hd = threadIdx.x;
    int h = hd >> 6, d = hd & 63;
    float s = 0.f;
    #pragma unroll 8
    for (int e = 0; e < 64; e++) s += wv[e*64 + d] * wo[(size_t)f*512 + h*64 + e];
    g_WvoTh[(size_t)f*512 + hd] = __float2half(s);
}
__global__ void prep_convw(const float* __restrict__ w) {
    int i = blockIdx.x * 512 + threadIdx.x;   // EMB_*KCONV / 512 blocks
    float2 a = *(const float2*)(w + i*2);
    *(__half2*)&g_cwh[i*2] = __floats2half2_rn(a.x, a.y);
}
// 8 elements/thread, vectorized
__global__ __launch_bounds__(512) void x2h(const float* __restrict__ x) {
    size_t i = (size_t)(blockIdx.x * 512 + threadIdx.x) * 8;
    float4 a = *(const float4*)(x + i);
    float4 b = *(const float4*)(x + i + 4);
    uint4 u;
    u.x = pack2(a.x, a.y); u.y = pack2(a.z, a.w);
    u.z = pack2(b.x, b.y); u.w = pack2(b.z, b.w);
    *(uint4*)&g_xh[i] = u;
}

// =================================================================
// Conv patch-embed GEMM, fp16 m16n8k16, implicit im2col.
//   M=18432, N=512, K=768.  BM=BN=128, BK=32 halves, 8 warps.
//   Word stride 20 (16 data + 4 pad) -> clean fragment loads.
// =================================================================
#define CWS 20
#define CONV_SMEM (2*128*CWS*2*4)   // 40960 B

__global__ __launch_bounds__(256, 2) void conv_f16(const float* __restrict__ bias) {
    extern __shared__ float sm[];
    uint32_t* AW = (uint32_t*)sm;
    uint32_t* BW = AW + 2*128*CWS;

    const int tid = threadIdx.x;
    const int lane = tid & 31;
    const int wr = tid >> 5, wm = wr & 1, wn = wr >> 1;
    const int g = lane >> 2, tig = lane & 3;
    const int m0 = blockIdx.y * 128, n0 = blockIdx.x * 128;

    // loader precompute: 2 chunks/thread each for A and B; v = tid + i*256
    int lrow[2], lkc[2];
    const __half* abase[2];
    const __half* bbase[2];
    #pragma unroll
    for (int i = 0; i < 2; i++) {
        int v = tid + i*256;
        int row = v >> 2, kc = v & 3;       // 128 rows x 4 chunks(8 halves)
        lrow[i] = row; lkc[i] = kc;
        int m = m0 + row;
        int bb = m / 576, p = m % 576;
        int py = p / 24, px = p % 24;
        abase[i] = g_xh + (size_t)bb*3*IMGW*IMGW + (size_t)(py*16)*IMGW + px*16;
        bbase[i] = g_cwh + (size_t)(n0 + row)*KCONV + kc*8;
    }

    auto load_tiles = [&](int buf, int t) {
        #pragma unroll
        for (int i = 0; i < 2; i++) {
            int kg = t*32 + lkc[i]*8;
            int c = kg >> 8, rem = kg & 255;
            int dy = rem >> 4, dx = rem & 15;   // dx in {0,8}
            const __half* ga = abase[i] + (size_t)c*(IMGW*IMGW) + dy*IMGW + dx;
            cp_async16(&AW[buf*128*CWS + lrow[i]*CWS + lkc[i]*4], ga);
            cp_async16(&BW[buf*128*CWS + lrow[i]*CWS + lkc[i]*4], bbase[i] + t*32);
        }
    };

    float acc[4][4][4] = {};

    load_tiles(0, 0);
    CP_COMMIT();
    const int nk = KCONV / 32;   // 24
    for (int t = 0; t < nk; t++) {
        int buf = t & 1;
        if (t + 1 < nk) load_tiles(buf ^ 1, t+1);
        CP_COMMIT();
        CP_WAIT(1);
        __syncthreads();

        const uint32_t* Ab = AW + buf*128*CWS;
        const uint32_t* Bb = BW + buf*128*CWS;
        #pragma unroll
        for (int ks = 0; ks < 2; ks++) {
            int w0 = ks*8;
            uint32_t af[4][4], bf[4][2];
            #pragma unroll
            for (int i = 0; i < 4; i++) {
                int r = wm*64 + i*16 + g;
                af[i][0] = Ab[(r  )*CWS + w0 + tig];
                af[i][1] = Ab[(r+8)*CWS + w0 + tig];
                af[i][2] = Ab[(r  )*CWS + w0 + tig + 4];
                af[i][3] = Ab[(r+8)*CWS + w0 + tig + 4];
            }
            #pragma unroll
            for (int j = 0; j < 4; j++) {
                int n = wn*32 + j*8 + g;
                bf[j][0] = Bb[n*CWS + w0 + tig];
                bf[j][1] = Bb[n*CWS + w0 + tig + 4];
            }
            #pragma unroll
            for (int i = 0; i < 4; i++)
                #pragma unroll
                for (int j = 0; j < 4; j++)
                    mma_f16(acc[i][j], af[i], bf[j][0], bf[j][1]);
        }
        __syncthreads();
    }

    #pragma unroll
    for (int i = 0; i < 4; i++) {
        int r = m0 + wm*64 + i*16 + g;
        #pragma unroll
        for (int j = 0; j < 4; j++) {
            int cc = n0 + wn*32 + j*8 + tig*2;
            float b0 = bias[cc], b1 = bias[cc+1];
            *(__half2*)&g_hh[(size_t)r*512 + cc]     = __floats2half2_rn(acc[i][j][0] + b0, acc[i][j][1] + b1);
            *(__half2*)&g_hh[(size_t)(r+8)*512 + cc] = __floats2half2_rn(acc[i][j][2] + b0, acc[i][j][3] + b1);
        }
    }
}

// =================================================================
// Flash attention, fp16 m16n8k16 (unchanged from R11 winner).
// =================================================================
#define AWS 36
#define KV_OFF   (96*AWS)
#define PS_OFF   (KV_OFF + 2*64*AWS)
#define MS_OFF   (PS_OFF + 96*AWS)
#define SS_OFF   (MS_OFF + 192)
#define ATTN_SMEM ((SS_OFF + 192)*4)  // 47616 B

__global__ __launch_bounds__(192, 3) void attn_f16() {
    extern __shared__ float sm[];
    uint32_t* QW = (uint32_t*)sm;
    uint32_t* KVW = QW + KV_OFF;
    uint32_t* PW = QW + PS_OFF;
    float* Msm = sm + MS_OFF;
    float* Ssm = sm + SS_OFF;

    const int qt = blockIdx.x, hh = blockIdx.y, b = blockIdx.z;
    const int tid = threadIdx.x;
    const int wr = tid >> 5, lane = tid & 31;
    const int wm = wr >> 1, wn = wr & 1;
    const int g = lane >> 2, tig = lane & 3;
    const size_t rowbase = (size_t)(b*SLEN)*EMB_ + hh*HD;
    const int rr[2] = { wm*32 + g, wm*32 + 16 + g };

    const int lm_row  = lane & 15;
    const int lm_colw = ((lane >> 4) & 1) * 4 + wn*16;

    auto loadKV = [&](int buf, int kt) {
        const __half* kb = g_hh + rowbase + (size_t)(kt*64)*EMB_;
        for (int v = tid; v < 512; v += 192) {
            int r = v >> 3, c8 = (v & 7);
            cp_async16(&KVW[buf*64*AWS + r*AWS + c8*4], kb + (size_t)r*EMB_ + c8*8);
        }
    };

    loadKV(0, 0);
    {
        const __half* hb = g_hh + rowbase + (size_t)(qt*96)*EMB_;
        for (int v = tid; v < 768; v += 192) {
            int r = v >> 3, c8 = (v & 7);
            cp_async16(&QW[r*AWS + c8*4], hb + (size_t)r*EMB_ + c8*8);
        }
        for (int v = tid; v < 512; v += 192) {
            int r = v >> 3, c8 = (v & 7);
            cp_async16(&PW[r*AWS + c8*4], g_Gh + r*64 + c8*8);
        }
    }
    CP_COMMIT();
    CP_WAIT(0);
    __syncthreads();

    // ---- Q = H @ G ----
    {
        float qc[2][4][4] = {};
        #pragma unroll
        for (int ks = 0; ks < 4; ks++) {
            int w0 = ks*8;
            uint32_t ha[2][4];
            #pragma unroll
            for (int i = 0; i < 2; i++) {
                ha[i][0] = QW[(rr[i]  )*AWS + w0 + tig];
                ha[i][1] = QW[(rr[i]+8)*AWS + w0 + tig];
                ha[i][2] = QW[(rr[i]  )*AWS + w0 + tig + 4];
                ha[i][3] = QW[(rr[i]+8)*AWS + w0 + tig + 4];
            }
            #pragma unroll
            for (int j = 0; j < 4; j++) {
                int n = wn*32 + j*8 + g;
                uint32_t b0 = PW[n*AWS + w0 + tig];
                uint32_t b1 = PW[n*AWS + w0 + tig + 4];
                mma_f16(qc[0][j], ha[0], b0, b1);
                mma_f16(qc[1][j], ha[1], b0, b1);
            }
        }
        __syncthreads();
        #pragma unroll
        for (int i = 0; i < 2; i++)
            #pragma unroll
            for (int j = 0; j < 4; j++) {
                int cw = wn*16 + j*4 + tig;
                QW[(rr[i]  )*AWS + cw] = pack2(qc[i][j][0], qc[i][j][1]);
                QW[(rr[i]+8)*AWS + cw] = pack2(qc[i][j][2], qc[i][j][3]);
            }
        __syncthreads();
    }

    float oacc[2][4][4] = {};
    float m_[2][2], l_[2][2];
    #pragma unroll
    for (int i = 0; i < 2; i++) { m_[i][0] = m_[i][1] = -3.0e38f; l_[i][0] = l_[i][1] = 0.f; }

    const uint32_t kv_base_addr = (uint32_t)__cvta_generic_to_shared(KVW);

    for (int kt = 0; kt < 9; kt++) {
        int buf = kt & 1;
        CP_WAIT(0);
        __syncthreads();

        if (kt + 1 < 9) { loadKV(buf ^ 1, kt + 1); CP_COMMIT(); }

        const uint32_t* KB = KVW + buf*64*AWS;
        const uint32_t kaddr = kv_base_addr + (buf*64*AWS)*4;

        float sacc[2][4][4] = {};
        #pragma unroll
        for (int ks = 0; ks < 4; ks++) {
            int w0 = ks*8;
            uint32_t a0[4], a1[4];
            a0[0] = QW[(rr[0]  )*AWS + w0 + tig];
            a0[1] = QW[(rr[0]+8)*AWS + w0 + tig];
            a0[2] = QW[(rr[0]  )*AWS + w0 + tig + 4];
            a0[3] = QW[(rr[0]+8)*AWS + w0 + tig + 4];
            a1[0] = QW[(rr[1]  )*AWS + w0 + tig];
            a1[1] = QW[(rr[1]+8)*AWS + w0 + tig];
            a1[2] = QW[(rr[1]  )*AWS + w0 + tig + 4];
            a1[3] = QW[(rr[1]+8)*AWS + w0 + tig + 4];
            #pragma unroll
            for (int j = 0; j < 4; j++) {
                int l = wn*32 + j*8 + g;
                uint32_t b0 = KB[l*AWS + w0 + tig];
                uint32_t b1 = KB[l*AWS + w0 + tig + 4];
                mma_f16(sacc[0][j], a0, b0, b1);
                mma_f16(sacc[1][j], a1, b0, b1);
            }
        }

        float pm[2][2];
        #pragma unroll
        for (int i = 0; i < 2; i++) {
            pm[i][0] = fmaxf(fmaxf(sacc[i][0][0], sacc[i][0][1]), fmaxf(sacc[i][1][0], sacc[i][1][1]));
            pm[i][0] = fmaxf(pm[i][0], fmaxf(fmaxf(sacc[i][2][0], sacc[i][2][1]), fmaxf(sacc[i][3][0], sacc[i][3][1])));
            pm[i][1] = fmaxf(fmaxf(sacc[i][0][2], sacc[i][0][3]), fmaxf(sacc[i][1][2], sacc[i][1][3]));
            pm[i][1] = fmaxf(pm[i][1], fmaxf(fmaxf(sacc[i][2][2], sacc[i][2][3]), fmaxf(sacc[i][3][2], sacc[i][3][3])));
            #pragma unroll
            for (int r = 0; r < 2; r++) {
                pm[i][r] = fmaxf(pm[i][r], __shfl_xor_sync(0xffffffffu, pm[i][r], 1));
                pm[i][r] = fmaxf(pm[i][r], __shfl_xor_sync(0xffffffffu, pm[i][r], 2));
            }
        }
        if (tig == 0) {
            #pragma unroll
            for (int i = 0; i < 2; i++) {
                Msm[(rr[i]  )*2 + wn] = pm[i][0];
                Msm[(rr[i]+8)*2 + wn] = pm[i][1];
            }
        }
        __syncthreads();

        float alpha[2][2];
        #pragma unroll
        for (int i = 0; i < 2; i++) {
            #pragma unroll
            for (int r = 0; r < 2; r++) {
                int row = rr[i] + r*8;
                float mt = fmaxf(Msm[row*2], Msm[row*2 + 1]);
                float mnew = fmaxf(m_[i][r], mt);
                alpha[i][r] = __expf(m_[i][r] - mnew);
                m_[i][r] = mnew;
            }
        }

        float psum[2][2] = {};
        #pragma unroll
        for (int i = 0; i < 2; i++)
            #pragma unroll
            for (int j = 0; j < 4; j++) {
                int cw = wn*16 + j*4 + tig;
                float p0 = __expf(sacc[i][j][0] - m_[i][0]);
                float p1 = __expf(sacc[i][j][1] - m_[i][0]);
                float p2 = __expf(sacc[i][j][2] - m_[i][1]);
                float p3 = __expf(sacc[i][j][3] - m_[i][1]);
                psum[i][0] += p0 + p1;
                psum[i][1] += p2 + p3;
                PW[(rr[i]  )*AWS + cw] = pack2(p0, p1);
                PW[(rr[i]+8)*AWS + cw] = pack2(p2, p3);
            }
        #pragma unroll
        for (int i = 0; i < 2; i++)
            #pragma unroll
            for (int r = 0; r < 2; r++) {
                psum[i][r] += __shfl_xor_sync(0xffffffffu, psum[i][r], 1);
                psum[i][r] += __shfl_xor_sync(0xffffffffu, psum[i][r], 2);
            }
        if (tig == 0) {
            #pragma unroll
            for (int i = 0; i < 2; i++) {
                Ssm[(rr[i]  )*2 + wn] = psum[i][0];
                Ssm[(rr[i]+8)*2 + wn] = psum[i][1];
            }
        }
        __syncthreads();

        #pragma unroll
        for (int i = 0; i < 2; i++) {
            #pragma unroll
            for (int r = 0; r < 2; r++) {
                int row = rr[i] + r*8;
                l_[i][r] = l_[i][r]*alpha[i][r] + Ssm[row*2] + Ssm[row*2 + 1];
            }
            #pragma unroll
            for (int j = 0; j < 4; j++) {
                oacc[i][j][0] *= alpha[i][0]; oacc[i][j][1] *= alpha[i][0];
                oacc[i][j][2] *= alpha[i][1]; oacc[i][j][3] *= alpha[i][1];
            }
        }

        #pragma unroll
        for (int ks = 0; ks < 4; ks++) {
            int w0 = ks*8;
            uint32_t ap[2][4];
            #pragma unroll
            for (int i = 0; i < 2; i++) {
                ap[i][0] = PW[(rr[i]  )*AWS + w0 + tig];
                ap[i][1] = PW[(rr[i]+8)*AWS + w0 + tig];
                ap[i][2] = PW[(rr[i]  )*AWS + w0 + tig + 4];
                ap[i][3] = PW[(rr[i]+8)*AWS + w0 + tig + 4];
            }
            #pragma unroll
            for (int jp = 0; jp < 2; jp++) {
                uint32_t r0, r1, r2, r3;
                uint32_t addr = kaddr + ((ks*16 + lm_row)*AWS + lm_colw + jp*8)*4;
                ldsm_x4_trans(r0, r1, r2, r3, addr);
                mma_f16(oacc[0][jp*2    ], ap[0], r0, r1);
                mma_f16(oacc[1][jp*2    ], ap[1], r0, r1);
                mma_f16(oacc[0][jp*2 + 1], ap[0], r2, r3);
                mma_f16(oacc[1][jp*2 + 1], ap[1], r2, r3);
            }
        }
    }

    __half* ob = g_ctxh + rowbase + (size_t)(qt*96)*EMB_;
    #pragma unroll
    for (int i = 0; i < 2; i++)
        #pragma unroll
        for (int r = 0; r < 2; r++) {
            int row = rr[i] + r*8;
            float inv = 1.0f / l_[i][r];
            #pragma unroll
            for (int j = 0; j < 4; j++) {
                int d = wn*32 + j*8 + tig*2;
                *(__half2*)&ob[(size_t)row*EMB_ + d] =
                    __floats2half2_rn(oacc[i][j][r*2]*inv, oacc[i][j][r*2+1]*inv);
            }
        }
}

// =================================================================
// Output projection, fp16 m16n8k16 (unchanged from R11 winner).
// =================================================================
#define PWS 20
#define PROJ_SMEM (2*128*PWS*2*4)   // 40960 B

__global__ __launch_bounds__(256, 2) void proj_f16(const float* __restrict__ bias,
                                                   float* __restrict__ C) {
    extern __shared__ float sm[];
    uint32_t* AW = (uint32_t*)sm;
    uint32_t* BW = AW + 2*128*PWS;

    const int tid = threadIdx.x;
    const int lane = tid & 31;
    const int wr = tid >> 5, wm = wr & 1, wn = wr >> 1;
    const int g = lane >> 2, tig = lane & 3;
    const int m0 = blockIdx.y * 128, n0 = blockIdx.x * 128;

    auto load_tiles = [&](int buf, int t) {
        #pragma unroll
        for (int i = 0; i < 2; i++) {
            int v = tid + i*256;
            int row = v >> 2, kc = v & 3;
            cp_async16(&AW[buf*128*PWS + row*PWS + kc*4],
                       g_ctxh + (size_t)(m0 + row)*512 + t*32 + kc*8);
            cp_async16(&BW[buf*128*PWS + row*PWS + kc*4],
                       g_WvoTh + (size_t)(n0 + row)*512 + t*32 + kc*8);
        }
    };

    float acc[4][4][4] = {};

    load_tiles(0, 0);
    CP_COMMIT();
    const int nk = 16;
    for (int t = 0; t < nk; t++) {
        int buf = t & 1;
        if (t + 1 < nk) load_tiles(buf ^ 1, t+1);
        CP_COMMIT();
        CP_WAIT(1);
        __syncthreads();

        const uint32_t* Ab = AW + buf*128*PWS;
        const uint32_t* Bb = BW + buf*128*PWS;
        #pragma unroll
        for (int ks = 0; ks < 2; ks++) {
            int w0 = ks*8;
            uint32_t af[4][4], bf[4][2];
            #pragma unroll
            for (int i = 0; i < 4; i++) {
                int r = wm*64 + i*16 + g;
                af[i][0] = Ab[(r  )*PWS + w0 + tig];
                af[i][1] = Ab[(r+8)*PWS + w0 + tig];
                af[i][2] = Ab[(r  )*PWS + w0 + tig + 4];
                af[i][3] = Ab[(r+8)*PWS + w0 + tig + 4];
            }
            #pragma unroll
            for (int j = 0; j < 4; j++) {
                int n = wn*32 + j*8 + g;
                bf[j][0] = Bb[n*PWS + w0 + tig];
                bf[j][1] = Bb[n*PWS + w0 + tig + 4];
            }
            #pragma unroll
            for (int i = 0; i < 4; i++)
                #pragma unroll
                for (int j = 0; j < 4; j++)
                    mma_f16(acc[i][j], af[i], bf[j][0], bf[j][1]);
        }
        __syncthreads();
    }

    #pragma unroll
    for (int i = 0; i < 4; i++) {
        int r = m0 + wm*64 + i*16 + g;
        #pragma unroll
        for (int j = 0; j < 4; j++) {
            int cc = n0 + wn*32 + j*8 + tig*2;
            float2 v0 = make_float2(acc[i][j][0] + bias[cc], acc[i][j][1] + bias[cc+1]);
            float2 v1 = make_float2(acc[i][j][2] + bias[cc], acc[i][j][3] + bias[cc+1]);
            *(float2*)&C[(size_t)r*512 + cc] = v0;
            *(float2*)&C[(size_t)(r+8)*512 + cc] = v1;
        }
    }
}

// =================================================================
extern "C" void kernel_launch(void* const* d_in, const int* in_sizes, int n_in,
                              void* d_out, int out_size) {
    (void)in_sizes; (void)n_in; (void)out_size;
    const float* x      = (const float*)d_in[0];
    const float* conv_w = (const float*)d_in[1];
    const float* conv_b = (const float*)d_in[2];
    const float* wq     = (const float*)d_in[3];
    const float* wk     = (const float*)d_in[4];
    const float* wv     = (const float*)d_in[5];
    const float* wo     = (const float*)d_in[6];
    const float* bo     = (const float*)d_in[7];
    float* out = (float*)d_out;

    cudaFuncSetAttribute(conv_f16, cudaFuncAttributeMaxDynamicSharedMemorySize, CONV_SMEM);
    cudaFuncSetAttribute(attn_f16, cudaFuncAttributeMaxDynamicSharedMemorySize, ATTN_SMEM);
    cudaFuncSetAttribute(proj_f16, cudaFuncAttributeMaxDynamicSharedMemorySize, PROJ_SMEM);

    x2h      <<<XELEM/(512*8), 512>>>(x);          // 3456 blocks
    prep_convw<<<EMB_*KCONV/1024, 512>>>(conv_w);  // 384 blocks
    prep_G   <<<64, 64>>>(wq, wk);
    prep_Wvo <<<512, 512>>>(wv, wo);
    conv_f16 <<<dim3(4, 144), 256, CONV_SMEM>>>(conv_b);
    attn_f16 <<<dim3(6, NHEAD, BATCH), 192, ATTN_SMEM>>>();
    proj_f16 <<<dim3(4, 144), 256, PROJ_SMEM>>>(bo, out);
}

// round 14
// speedup vs baseline: 1.7036x; 1.0080x over previous
#include <cuda_runtime.h>
#include <cuda_fp16.h>
#include <math.h>
#include <stdint.h>

// Shapes
#define BATCH   32
#define SLEN    576
#define EMB_    512
#define NHEAD   8
#define HD      64
#define TOK     (BATCH*SLEN) // 18432
#define IMGW    384
#define KCONV   768
#define XELEM   (BATCH*3*IMGW*IMGW)   // 14155776

// -------- scratch (device globals) --------
__device__ __half g_xh  [XELEM];      // x in fp16
__device__ __half g_cwh [EMB_*KCONV]; // conv_w in fp16
__device__ __half g_hh  [TOK*EMB_];   // patch embeddings (fp16)
__device__ __half g_ctxh[TOK*EMB_];   // att @ h (fp16)
__device__ __half g_Gh  [HD*HD];      // folded Wq^T Wk * 0.125 (fp16)
__device__ __half g_WvoTh[EMB_*EMB_]; // folded Wv->Wo (fp16)

// ---------------- helpers ----------------
__device__ __forceinline__ uint32_t pack2(float a, float b) {
    __half2 h = __floats2half2_rn(a, b);
    return *(uint32_t*)&h;
}
__device__ __forceinline__ void mma_f16(float* c, const uint32_t* a, uint32_t b0, uint32_t b1) {
    asm volatile(
        "mma.sync.aligned.m16n8k16.row.col.f32.f16.f16.f32 "
        "{%0,%1,%2,%3}, {%4,%5,%6,%7}, {%8,%9}, {%0,%1,%2,%3};\n"
        : "+f"(c[0]), "+f"(c[1]), "+f"(c[2]), "+f"(c[3])
        : "r"(a[0]), "r"(a[1]), "r"(a[2]), "r"(a[3]), "r"(b0), "r"(b1));
}
__device__ __forceinline__ void ldsm_x4_trans(uint32_t& r0, uint32_t& r1, uint32_t& r2, uint32_t& r3,
                                              uint32_t addr) {
    asm volatile("ldmatrix.sync.aligned.m8n8.x4.trans.shared.b16 {%0,%1,%2,%3}, [%4];"
        : "=r"(r0), "=r"(r1), "=r"(r2), "=r"(r3) : "r"(addr));
}
__device__ __forceinline__ void cp_async16(void* smem, const void* gmem) {
    uint32_t s = (uint32_t)__cvta_generic_to_shared(smem);
    asm volatile("cp.async.cg.shared.global [%0], [%1], 16;\n" :: "r"(s), "l"(gmem));
}
#define CP_COMMIT() asm volatile("cp.async.commit_group;\n")
#define CP_WAIT(n)  asm volatile("cp.async.wait_group %0;\n" :: "n"(n))

// =================================================================
// Preps
// =================================================================
__global__ void prep_G(const float* __restrict__ wq, const float* __restrict__ wk) {
    int dp = blockIdx.x, d = threadIdx.x;
    float s = 0.f;
    #pragma unroll 8
    for (int e = 0; e < 64; e++) s += wq[e*64 + d] * wk[e*64 + dp];
    g_Gh[dp*64 + d] = __float2half(0.125f * s);
}
// wv staged in smem; 8 outputs/thread; 128 blocks x 256 thr
__global__ __launch_bounds__(256) void prep_Wvo(const float* __restrict__ wv,
                                                const float* __restrict__ wo) {
    __shared__ float wvs[64][65];
    int tid = threadIdx.x;
    for (int i = tid; i < 4096; i += 256) wvs[i >> 6][i & 63] = wv[i];
    __syncthreads();
    int f  = blockIdx.x*4 + (tid >> 6);
    int h  = (tid >> 3) & 7;
    int d0 = (tid & 7) * 8;
    const float* worow = wo + (size_t)f*512 + h*64;
    float acc[8] = {};
    #pragma unroll 8
    for (int e = 0; e < 64; e++) {
        float woe = worow[e];
        #pragma unroll
        for (int d = 0; d < 8; d++) acc[d] = fmaf(woe, wvs[e][d0 + d], acc[d]);
    }
    __half* dst = g_WvoTh + (size_t)f*512 + h*64 + d0;
    #pragma unroll
    for (int d = 0; d < 8; d += 2)
        *(__half2*)&dst[d] = __floats2half2_rn(acc[d], acc[d+1]);
}
__global__ void prep_convw(const float* __restrict__ w) {
    int i = blockIdx.x * 512 + threadIdx.x;
    float2 a = *(const float2*)(w + i*2);
    *(__half2*)&g_cwh[i*2] = __floats2half2_rn(a.x, a.y);
}
__global__ __launch_bounds__(512) void x2h(const float* __restrict__ x) {
    size_t i = (size_t)(blockIdx.x * 512 + threadIdx.x) * 8;
    float4 a = *(const float4*)(x + i);
    float4 b = *(const float4*)(x + i + 4);
    uint4 u;
    u.x = pack2(a.x, a.y); u.y = pack2(a.z, a.w);
    u.z = pack2(b.x, b.y); u.w = pack2(b.z, b.w);
    *(uint4*)&g_xh[i] = u;
}

// =================================================================
// Conv patch-embed GEMM, fp16, implicit im2col. BK=64 halves.
//   M=18432, N=512, K=768.  12 k-iterations.
// =================================================================
#define CWS 36
#define CONV_SMEM (2*128*CWS*2*4)   // 73728 B

__global__ __launch_bounds__(256, 2) void conv_f16(const float* __restrict__ bias) {
    extern __shared__ float sm[];
    uint32_t* AW = (uint32_t*)sm;
    uint32_t* BW = AW + 2*128*CWS;

    const int tid = threadIdx.x;
    const int lane = tid & 31;
    const int wr = tid >> 5, wm = wr & 1, wn = wr >> 1;
    const int g = lane >> 2, tig = lane & 3;
    const int m0 = blockIdx.y * 128, n0 = blockIdx.x * 128;

    int lrow[4], lkc[4];
    const __half* abase[4];
    const __half* bbase[4];
    #pragma unroll
    for (int i = 0; i < 4; i++) {
        int v = tid + i*256;
        int row = v >> 3, kc = v & 7;
        lrow[i] = row; lkc[i] = kc;
        int m = m0 + row;
        int bb = m / 576, p = m % 576;
        int py = p / 24, px = p % 24;
        abase[i] = g_xh + (size_t)bb*3*IMGW*IMGW + (size_t)(py*16)*IMGW + px*16;
        bbase[i] = g_cwh + (size_t)(n0 + row)*KCONV + kc*8;
    }

    auto load_tiles = [&](int buf, int t) {
        #pragma unroll
        for (int i = 0; i < 4; i++) {
            int kg = t*64 + lkc[i]*8;
            int c = kg >> 8, rem = kg & 255;
            int dy = rem >> 4, dx = rem & 15;   // dx in {0,8}
            const __half* ga = abase[i] + (size_t)c*(IMGW*IMGW) + dy*IMGW + dx;
            cp_async16(&AW[buf*128*CWS + lrow[i]*CWS + lkc[i]*4], ga);
            cp_async16(&BW[buf*128*CWS + lrow[i]*CWS + lkc[i]*4], bbase[i] + t*64);
        }
    };

    float acc[4][4][4] = {};

    load_tiles(0, 0);
    CP_COMMIT();
    const int nk = KCONV / 64;   // 12
    for (int t = 0; t < nk; t++) {
        int buf = t & 1;
        if (t + 1 < nk) load_tiles(buf ^ 1, t+1);
        CP_COMMIT();
        CP_WAIT(1);
        __syncthreads();

        const uint32_t* Ab = AW + buf*128*CWS;
        const uint32_t* Bb = BW + buf*128*CWS;
        #pragma unroll
        for (int ks = 0; ks < 4; ks++) {
            int w0 = ks*8;
            uint32_t af[4][4], bf[4][2];
            #pragma unroll
            for (int i = 0; i < 4; i++) {
                int r = wm*64 + i*16 + g;
                af[i][0] = Ab[(r  )*CWS + w0 + tig];
                af[i][1] = Ab[(r+8)*CWS + w0 + tig];
                af[i][2] = Ab[(r  )*CWS + w0 + tig + 4];
                af[i][3] = Ab[(r+8)*CWS + w0 + tig + 4];
            }
            #pragma unroll
            for (int j = 0; j < 4; j++) {
                int n = wn*32 + j*8 + g;
                bf[j][0] = Bb[n*CWS + w0 + tig];
                bf[j][1] = Bb[n*CWS + w0 + tig + 4];
            }
            #pragma unroll
            for (int i = 0; i < 4; i++)
                #pragma unroll
                for (int j = 0; j < 4; j++)
                    mma_f16(acc[i][j], af[i], bf[j][0], bf[j][1]);
        }
        __syncthreads();
    }

    #pragma unroll
    for (int i = 0; i < 4; i++) {
        int r = m0 + wm*64 + i*16 + g;
        #pragma unroll
        for (int j = 0; j < 4; j++) {
            int cc = n0 + wn*32 + j*8 + tig*2;
            float b0 = bias[cc], b1 = bias[cc+1];
            *(__half2*)&g_hh[(size_t)r*512 + cc]     = __floats2half2_rn(acc[i][j][0] + b0, acc[i][j][1] + b1);
            *(__half2*)&g_hh[(size_t)(r+8)*512 + cc] = __floats2half2_rn(acc[i][j][2] + b0, acc[i][j][3] + b1);
        }
    }
}

// =================================================================
// Flash attention, fp16 m16n8k16, KV tile 96 rows (6 tiles).
//   Qs/KV stride 36 words; P stride 52 words (both conflict-free).
// =================================================================
#define AWS 36
#define PWA 52
#define KT  96
#define KV_OFF   (96*AWS)                 // Qs 96x36
#define PS_OFF   (KV_OFF + 2*KT*AWS)      // KV 2x96x36
#define MS_OFF   (PS_OFF + 96*PWA)        // P 96x52
#define SS_OFF   (MS_OFF + 192)
#define ATTN_SMEM ((SS_OFF + 192)*4)      // 62976 B

__global__ __launch_bounds__(192, 3) void attn_f16() {
    extern __shared__ float sm[];
    uint32_t* QW = (uint32_t*)sm;
    uint32_t* KVW = QW + KV_OFF;
    uint32_t* PW = QW + PS_OFF;
    float* Msm = sm + MS_OFF;
    float* Ssm = sm + SS_OFF;

    const int qt = blockIdx.x, hh = blockIdx.y, b = blockIdx.z;
    const int tid = threadIdx.x;
    const int wr = tid >> 5, lane = tid & 31;
    const int wm = wr >> 1, wn = wr & 1;
    const int g = lane >> 2, tig = lane & 3;
    const size_t rowbase = (size_t)(b*SLEN)*EMB_ + hh*HD;
    const int rr[2] = { wm*32 + g, wm*32 + 16 + g };

    const int lm_row  = lane & 15;
    const int lm_colw = ((lane >> 4) & 1) * 4 + wn*16;

    auto loadKV = [&](int buf, int kt) {
        const __half* kb = g_hh + rowbase + (size_t)(kt*KT)*EMB_;
        for (int v = tid; v < KT*8; v += 192) {
            int r = v >> 3, c8 = (v & 7);
            cp_async16(&KVW[buf*KT*AWS + r*AWS + c8*4], kb + (size_t)r*EMB_ + c8*8);
        }
    };

    // prologue: KV tile 0 -> buf0, H -> QW, G -> PW (stride 52)
    loadKV(0, 0);
    {
        const __half* hb = g_hh + rowbase + (size_t)(qt*96)*EMB_;
        for (int v = tid; v < 768; v += 192) {
            int r = v >> 3, c8 = (v & 7);
            cp_async16(&QW[r*AWS + c8*4], hb + (size_t)r*EMB_ + c8*8);
        }
        for (int v = tid; v < 512; v += 192) {
            int r = v >> 3, c8 = (v & 7);
            cp_async16(&PW[r*PWA + c8*4], g_Gh + r*64 + c8*8);
        }
    }
    CP_COMMIT();
    CP_WAIT(0);
    __syncthreads();

    // ---- Q = H @ G ----
    {
        float qc[2][4][4] = {};
        #pragma unroll
        for (int ks = 0; ks < 4; ks++) {
            int w0 = ks*8;
            uint32_t ha[2][4];
            #pragma unroll
            for (int i = 0; i < 2; i++) {
                ha[i][0] = QW[(rr[i]  )*AWS + w0 + tig];
                ha[i][1] = QW[(rr[i]+8)*AWS + w0 + tig];
                ha[i][2] = QW[(rr[i]  )*AWS + w0 + tig + 4];
                ha[i][3] = QW[(rr[i]+8)*AWS + w0 + tig + 4];
            }
            #pragma unroll
            for (int j = 0; j < 4; j++) {
                int n = wn*32 + j*8 + g;
                uint32_t b0 = PW[n*PWA + w0 + tig];
                uint32_t b1 = PW[n*PWA + w0 + tig + 4];
                mma_f16(qc[0][j], ha[0], b0, b1);
                mma_f16(qc[1][j], ha[1], b0, b1);
            }
        }
        __syncthreads();   // done reading H (QW) and G (PW)
        #pragma unroll
        for (int i = 0; i < 2; i++)
            #pragma unroll
            for (int j = 0; j < 4; j++) {
                int cw = wn*16 + j*4 + tig;
                QW[(rr[i]  )*AWS + cw] = pack2(qc[i][j][0], qc[i][j][1]);
                QW[(rr[i]+8)*AWS + cw] = pack2(qc[i][j][2], qc[i][j][3]);
            }
        __syncthreads();
    }

    float oacc[2][4][4] = {};
    float m_[2][2], l_[2][2];
    #pragma unroll
    for (int i = 0; i < 2; i++) { m_[i][0] = m_[i][1] = -3.0e38f; l_[i][0] = l_[i][1] = 0.f; }

    const uint32_t kv_base_addr = (uint32_t)__cvta_generic_to_shared(KVW);

    for (int kt = 0; kt < 6; kt++) {
        int buf = kt & 1;
        CP_WAIT(0);
        __syncthreads();

        if (kt + 1 < 6) { loadKV(buf ^ 1, kt + 1); CP_COMMIT(); }

        const uint32_t* KB = KVW + buf*KT*AWS;
        const uint32_t kaddr = kv_base_addr + (buf*KT*AWS)*4;

        // ---- S = Q K^T : warp covers 48 of 96 l-cols ----
        float sacc[2][6][4] = {};
        #pragma unroll
        for (int ks = 0; ks < 4; ks++) {
            int w0 = ks*8;
            uint32_t a0[4], a1[4];
            a0[0] = QW[(rr[0]  )*AWS + w0 + tig];
            a0[1] = QW[(rr[0]+8)*AWS + w0 + tig];
            a0[2] = QW[(rr[0]  )*AWS + w0 + tig + 4];
            a0[3] = QW[(rr[0]+8)*AWS + w0 + tig + 4];
            a1[0] = QW[(rr[1]  )*AWS + w0 + tig];
            a1[1] = QW[(rr[1]+8)*AWS + w0 + tig];
            a1[2] = QW[(rr[1]  )*AWS + w0 + tig + 4];
            a1[3] = QW[(rr[1]+8)*AWS + w0 + tig + 4];
            #pragma unroll
            for (int j = 0; j < 6; j++) {
                int l = wn*48 + j*8 + g;
                uint32_t b0 = KB[l*AWS + w0 + tig];
                uint32_t b1 = KB[l*AWS + w0 + tig + 4];
                mma_f16(sacc[0][j], a0, b0, b1);
                mma_f16(sacc[1][j], a1, b0, b1);
            }
        }

        // ---- partial row max over 6 j-tiles, quad-reduce, exchange ----
        float pm[2][2];
        #pragma unroll
        for (int i = 0; i < 2; i++) {
            pm[i][0] = -3.0e38f; pm[i][1] = -3.0e38f;
            #pragma unroll
            for (int j = 0; j < 6; j++) {
                pm[i][0] = fmaxf(pm[i][0], fmaxf(sacc[i][j][0], sacc[i][j][1]));
                pm[i][1] = fmaxf(pm[i][1], fmaxf(sacc[i][j][2], sacc[i][j][3]));
            }
            #pragma unroll
            for (int r = 0; r < 2; r++) {
                pm[i][r] = fmaxf(pm[i][r], __shfl_xor_sync(0xffffffffu, pm[i][r], 1));
                pm[i][r] = fmaxf(pm[i][r], __shfl_xor_sync(0xffffffffu, pm[i][r], 2));
            }
        }
        if (tig == 0) {
            #pragma unroll
            for (int i = 0; i < 2; i++) {
                Msm[(rr[i]  )*2 + wn] = pm[i][0];
                Msm[(rr[i]+8)*2 + wn] = pm[i][1];
            }
        }
        __syncthreads();

        float alpha[2][2];
        #pragma unroll
        for (int i = 0; i < 2; i++) {
            #pragma unroll
            for (int r = 0; r < 2; r++) {
                int row = rr[i] + r*8;
                float mt = fmaxf(Msm[row*2], Msm[row*2 + 1]);
                float mnew = fmaxf(m_[i][r], mt);
                alpha[i][r] = __expf(m_[i][r] - mnew);
                m_[i][r] = mnew;
            }
        }

        // ---- p = exp(s-m) -> PW (stride 52), partial sums, exchange ----
        float psum[2][2] = {};
        #pragma unroll
        for (int i = 0; i < 2; i++)
            #pragma unroll
            for (int j = 0; j < 6; j++) {
                int cw = wn*24 + j*4 + tig;
                float p0 = __expf(sacc[i][j][0] - m_[i][0]);
                float p1 = __expf(sacc[i][j][1] - m_[i][0]);
                float p2 = __expf(sacc[i][j][2] - m_[i][1]);
                float p3 = __expf(sacc[i][j][3] - m_[i][1]);
                psum[i][0] += p0 + p1;
                psum[i][1] += p2 + p3;
                PW[(rr[i]  )*PWA + cw] = pack2(p0, p1);
                PW[(rr[i]+8)*PWA + cw] = pack2(p2, p3);
            }
        #pragma unroll
        for (int i = 0; i < 2; i++)
            #pragma unroll
            for (int r = 0; r < 2; r++) {
                psum[i][r] += __shfl_xor_sync(0xffffffffu, psum[i][r], 1);
                psum[i][r] += __shfl_xor_sync(0xffffffffu, psum[i][r], 2);
            }
        if (tig == 0) {
            #pragma unroll
            for (int i = 0; i < 2; i++) {
                Ssm[(rr[i]  )*2 + wn] = psum[i][0];
                Ssm[(rr[i]+8)*2 + wn] = psum[i][1];
            }
        }
        __syncthreads();

        #pragma unroll
        for (int i = 0; i < 2; i++) {
            #pragma unroll
            for (int r = 0; r < 2; r++) {
                int row = rr[i] + r*8;
                l_[i][r] = l_[i][r]*alpha[i][r] + Ssm[row*2] + Ssm[row*2 + 1];
            }
            #pragma unroll
            for (int j = 0; j < 4; j++) {
                oacc[i][j][0] *= alpha[i][0]; oacc[i][j][1] *= alpha[i][0];
                oacc[i][j][2] *= alpha[i][1]; oacc[i][j][3] *= alpha[i][1];
            }
        }

        // ---- O += P V : 6 ks steps over 96 l ----
        #pragma unroll
        for (int ks = 0; ks < 6; ks++) {
            int w0 = ks*8;
            uint32_t ap[2][4];
            #pragma unroll
            for (int i = 0; i < 2; i++) {
                ap[i][0] = PW[(rr[i]  )*PWA + w0 + tig];
                ap[i][1] = PW[(rr[i]+8)*PWA + w0 + tig];
                ap[i][2] = PW[(rr[i]  )*PWA + w0 + tig + 4];
                ap[i][3] = PW[(rr[i]+8)*PWA + w0 + tig + 4];
            }
            #pragma unroll
            for (int jp = 0; jp < 2; jp++) {
                uint32_t r0, r1, r2, r3;
                uint32_t addr = kaddr + ((ks*16 + lm_row)*AWS + lm_colw + jp*8)*4;
                ldsm_x4_trans(r0, r1, r2, r3, addr);
                mma_f16(oacc[0][jp*2    ], ap[0], r0, r1);
                mma_f16(oacc[1][jp*2    ], ap[1], r0, r1);
                mma_f16(oacc[0][jp*2 + 1], ap[0], r2, r3);
                mma_f16(oacc[1][jp*2 + 1], ap[1], r2, r3);
            }
        }
    }

    __half* ob = g_ctxh + rowbase + (size_t)(qt*96)*EMB_;
    #pragma unroll
    for (int i = 0; i < 2; i++)
        #pragma unroll
        for (int r = 0; r < 2; r++) {
            int row = rr[i] + r*8;
            float inv = 1.0f / l_[i][r];
            #pragma unroll
            for (int j = 0; j < 4; j++) {
                int d = wn*32 + j*8 + tig*2;
                *(__half2*)&ob[(size_t)row*EMB_ + d] =
                    __floats2half2_rn(oacc[i][j][r*2]*inv, oacc[i][j][r*2+1]*inv);
            }
        }
}

// =================================================================
// Output projection, fp16, BK=64 halves. M=18432, N=512, K=512.
// =================================================================
#define PWS 36
#define PROJ_SMEM (2*128*PWS*2*4)   // 73728 B

__global__ __launch_bounds__(256, 2) void proj_f16(const float* __restrict__ bias,
                                                   float* __restrict__ C) {
    extern __shared__ float sm[];
    uint32_t* AW = (uint32_t*)sm;
    uint32_t* BW = AW + 2*128*PWS;

    const int tid = threadIdx.x;
    const int lane = tid & 31;
    const int wr = tid >> 5, wm = wr & 1, wn = wr >> 1;
    const int g = lane >> 2, tig = lane & 3;
    const int m0 = blockIdx.y * 128, n0 = blockIdx.x * 128;

    auto load_tiles = [&](int buf, int t) {
        #pragma unroll
        for (int i = 0; i < 4; i++) {
            int v = tid + i*256;
            int row = v >> 3, kc = v & 7;
            cp_async16(&AW[buf*128*PWS + row*PWS + kc*4],
                       g_ctxh + (size_t)(m0 + row)*512 + t*64 + kc*8);
            cp_async16(&BW[buf*128*PWS + row*PWS + kc*4],
                       g_WvoTh + (size_t)(n0 + row)*512 + t*64 + kc*8);
        }
    };

    float acc[4][4][4] = {};

    load_tiles(0, 0);
    CP_COMMIT();
    const int nk = 8;
    for (int t = 0; t < nk; t++) {
        int buf = t & 1;
        if (t + 1 < nk) load_tiles(buf ^ 1, t+1);
        CP_COMMIT();
        CP_WAIT(1);
        __syncthreads();

        const uint32_t* Ab = AW + buf*128*PWS;
        const uint32_t* Bb = BW + buf*128*PWS;
        #pragma unroll
        for (int ks = 0; ks < 4; ks++) {
            int w0 = ks*8;
            uint32_t af[4][4], bf[4][2];
            #pragma unroll
            for (int i = 0; i < 4; i++) {
                int r = wm*64 + i*16 + g;
                af[i][0] = Ab[(r  )*PWS + w0 + tig];
                af[i][1] = Ab[(r+8)*PWS + w0 + tig];
                af[i][2] = Ab[(r  )*PWS + w0 + tig + 4];
                af[i][3] = Ab[(r+8)*PWS + w0 + tig + 4];
            }
            #pragma unroll
            for (int j = 0; j < 4; j++) {
                int n = wn*32 + j*8 + g;
                bf[j][0] = Bb[n*PWS + w0 + tig];
                bf[j][1] = Bb[n*PWS + w0 + tig + 4];
            }
            #pragma unroll
            for (int i = 0; i < 4; i++)
                #pragma unroll
                for (int j = 0; j < 4; j++)
                    mma_f16(acc[i][j], af[i], bf[j][0], bf[j][1]);
        }
        __syncthreads();
    }

    #pragma unroll
    for (int i = 0; i < 4; i++) {
        int r = m0 + wm*64 + i*16 + g;
        #pragma unroll
        for (int j = 0; j < 4; j++) {
            int cc = n0 + wn*32 + j*8 + tig*2;
            float2 v0 = make_float2(acc[i][j][0] + bias[cc], acc[i][j][1] + bias[cc+1]);
            float2 v1 = make_float2(acc[i][j][2] + bias[cc], acc[i][j][3] + bias[cc+1]);
            *(float2*)&C[(size_t)r*512 + cc] = v0;
            *(float2*)&C[(size_t)(r+8)*512 + cc] = v1;
        }
    }
}

// =================================================================
extern "C" void kernel_launch(void* const* d_in, const int* in_sizes, int n_in,
                              void* d_out, int out_size) {
    (void)in_sizes; (void)n_in; (void)out_size;
    const float* x      = (const float*)d_in[0];
    const float* conv_w = (const float*)d_in[1];
    const float* conv_b = (const float*)d_in[2];
    const float* wq     = (const float*)d_in[3];
    const float* wk     = (const float*)d_in[4];
    const float* wv     = (const float*)d_in[5];
    const float* wo     = (const float*)d_in[6];
    const float* bo     = (const float*)d_in[7];
    float* out = (float*)d_out;

    cudaFuncSetAttribute(conv_f16, cudaFuncAttributeMaxDynamicSharedMemorySize, CONV_SMEM);
    cudaFuncSetAttribute(attn_f16, cudaFuncAttributeMaxDynamicSharedMemorySize, ATTN_SMEM);
    cudaFuncSetAttribute(proj_f16, cudaFuncAttributeMaxDynamicSharedMemorySize, PROJ_SMEM);

    x2h       <<<XELEM/(512*8), 512>>>(x);
    prep_convw<<<EMB_*KCONV/1024, 512>>>(conv_w);
    prep_G    <<<64, 64>>>(wq, wk);
    prep_Wvo  <<<128, 256>>>(wv, wo);
    conv_f16  <<<dim3(4, 144), 256, CONV_SMEM>>>(conv_b);
    attn_f16  <<<dim3(6, NHEAD, BATCH), 192, ATTN_SMEM>>>();
    proj_f16  <<<dim3(4, 144), 256, PROJ_SMEM>>>(bo, out);
}

// round 16
// speedup vs baseline: 1.7171x; 1.0079x over previous
#include <cuda_runtime.h>
#include <cuda_fp16.h>
#include <math.h>
#include <stdint.h>

// Shapes
#define BATCH   32
#define SLEN    576
#define EMB_    512
#define NHEAD   8
#define HD      64
#define TOK     (BATCH*SLEN) // 18432
#define IMGW    384
#define KCONV   768
#define XELEM   (BATCH*3*IMGW*IMGW)   // 14155776

// -------- scratch (device globals) --------
__device__ __half g_xh  [XELEM];      // x in fp16
__device__ __half g_cwh [EMB_*KCONV]; // conv_w in fp16
__device__ __half g_hh  [TOK*EMB_];   // patch embeddings (fp16)
__device__ __half g_ctxh[TOK*EMB_];   // att @ h (fp16)
__device__ __half g_Gh  [HD*HD];      // folded Wq^T Wk * 0.125 (fp16)
__device__ __half g_WvoTh[EMB_*EMB_]; // folded Wv->Wo (fp16)

// ---------------- helpers ----------------
__device__ __forceinline__ uint32_t pack2(float a, float b) {
    __half2 h = __floats2half2_rn(a, b);
    return *(uint32_t*)&h;
}
__device__ __forceinline__ void mma_f16(float* c, const uint32_t* a, uint32_t b0, uint32_t b1) {
    asm volatile(
        "mma.sync.aligned.m16n8k16.row.col.f32.f16.f16.f32 "
        "{%0,%1,%2,%3}, {%4,%5,%6,%7}, {%8,%9}, {%0,%1,%2,%3};\n"
        : "+f"(c[0]), "+f"(c[1]), "+f"(c[2]), "+f"(c[3])
        : "r"(a[0]), "r"(a[1]), "r"(a[2]), "r"(a[3]), "r"(b0), "r"(b1));
}
__device__ __forceinline__ void ldsm_x4_trans(uint32_t& r0, uint32_t& r1, uint32_t& r2, uint32_t& r3,
                                              uint32_t addr) {
    asm volatile("ldmatrix.sync.aligned.m8n8.x4.trans.shared.b16 {%0,%1,%2,%3}, [%4];"
        : "=r"(r0), "=r"(r1), "=r"(r2), "=r"(r3) : "r"(addr));
}
__device__ __forceinline__ void cp_async16(void* smem, const void* gmem) {
    uint32_t s = (uint32_t)__cvta_generic_to_shared(smem);
    asm volatile("cp.async.cg.shared.global [%0], [%1], 16;\n" :: "r"(s), "l"(gmem));
}
#define CP_COMMIT() asm volatile("cp.async.commit_group;\n")
#define CP_WAIT(n)  asm volatile("cp.async.wait_group %0;\n" :: "n"(n))

// =================================================================
// Preps
// =================================================================
__global__ void prep_G(const float* __restrict__ wq, const float* __restrict__ wk) {
    int dp = blockIdx.x, d = threadIdx.x;
    float s = 0.f;
    #pragma unroll 8
    for (int e = 0; e < 64; e++) s += wq[e*64 + d] * wk[e*64 + dp];
    g_Gh[dp*64 + d] = __float2half(0.125f * s);
}
// one block per output row f: wv + wo-row staged in smem; 2 outputs/thread
__global__ __launch_bounds__(256) void prep_Wvo(const float* __restrict__ wv,
                                                const float* __restrict__ wo) {
    __shared__ float wvs[64][65];
    __shared__ float wos[512];
    int tid = threadIdx.x, f = blockIdx.x;
    for (int i = tid; i < 4096; i += 256) wvs[i >> 6][i & 63] = wv[i];
    for (int i = tid; i < 512; i += 256) wos[i] = wo[(size_t)f*512 + i];
    __syncthreads();
    int h = tid >> 5, d0 = (tid & 31) * 2;
    float a0 = 0.f, a1 = 0.f;
    #pragma unroll 8
    for (int e = 0; e < 64; e++) {
        float woe = wos[h*64 + e];
        a0 = fmaf(woe, wvs[e][d0], a0);
        a1 = fmaf(woe, wvs[e][d0+1], a1);
    }
    *(__half2*)&g_WvoTh[(size_t)f*512 + h*64 + d0] = __floats2half2_rn(a0, a1);
}
__global__ void prep_convw(const float* __restrict__ w) {
    int i = blockIdx.x * 512 + threadIdx.x;
    float2 a = *(const float2*)(w + i*2);
    *(__half2*)&g_cwh[i*2] = __floats2half2_rn(a.x, a.y);
}
__global__ __launch_bounds__(512) void x2h(const float* __restrict__ x) {
    size_t i = (size_t)(blockIdx.x * 512 + threadIdx.x) * 8;
    float4 a = *(const float4*)(x + i);
    float4 b = *(const float4*)(x + i + 4);
    uint4 u;
    u.x = pack2(a.x, a.y); u.y = pack2(a.z, a.w);
    u.z = pack2(b.x, b.y); u.w = pack2(b.z, b.w);
    *(uint4*)&g_xh[i] = u;
}

// =================================================================
// Conv patch-embed GEMM, fp16, implicit im2col. BK=64 halves.
//   M=18432, N=512, K=768.  12 k-iterations.
// =================================================================
#define CWS 36
#define CONV_SMEM (2*128*CWS*2*4)   // 73728 B

__global__ __launch_bounds__(256, 2) void conv_f16(const float* __restrict__ bias) {
    extern __shared__ float sm[];
    uint32_t* AW = (uint32_t*)sm;
    uint32_t* BW = AW + 2*128*CWS;

    const int tid = threadIdx.x;
    const int lane = tid & 31;
    const int wr = tid >> 5, wm = wr & 1, wn = wr >> 1;
    const int g = lane >> 2, tig = lane & 3;
    const int m0 = blockIdx.y * 128, n0 = blockIdx.x * 128;

    int lrow[4], lkc[4];
    const __half* abase[4];
    const __half* bbase[4];
    #pragma unroll
    for (int i = 0; i < 4; i++) {
        int v = tid + i*256;
        int row = v >> 3, kc = v & 7;
        lrow[i] = row; lkc[i] = kc;
        int m = m0 + row;
        int bb = m / 576, p = m % 576;
        int py = p / 24, px = p % 24;
        abase[i] = g_xh + (size_t)bb*3*IMGW*IMGW + (size_t)(py*16)*IMGW + px*16;
        bbase[i] = g_cwh + (size_t)(n0 + row)*KCONV + kc*8;
    }

    auto load_tiles = [&](int buf, int t) {
        #pragma unroll
        for (int i = 0; i < 4; i++) {
            int kg = t*64 + lkc[i]*8;
            int c = kg >> 8, rem = kg & 255;
            int dy = rem >> 4, dx = rem & 15;   // dx in {0,8}
            const __half* ga = abase[i] + (size_t)c*(IMGW*IMGW) + dy*IMGW + dx;
            cp_async16(&AW[buf*128*CWS + lrow[i]*CWS + lkc[i]*4], ga);
            cp_async16(&BW[buf*128*CWS + lrow[i]*CWS + lkc[i]*4], bbase[i] + t*64);
        }
    };

    float acc[4][4][4] = {};

    load_tiles(0, 0);
    CP_COMMIT();
    const int nk = KCONV / 64;   // 12
    for (int t = 0; t < nk; t++) {
        int buf = t & 1;
        if (t + 1 < nk) load_tiles(buf ^ 1, t+1);
        CP_COMMIT();
        CP_WAIT(1);
        __syncthreads();

        const uint32_t* Ab = AW + buf*128*CWS;
        const uint32_t* Bb = BW + buf*128*CWS;
        #pragma unroll
        for (int ks = 0; ks < 4; ks++) {
            int w0 = ks*8;
            uint32_t af[4][4], bf[4][2];
            #pragma unroll
            for (int i = 0; i < 4; i++) {
                int r = wm*64 + i*16 + g;
                af[i][0] = Ab[(r  )*CWS + w0 + tig];
                af[i][1] = Ab[(r+8)*CWS + w0 + tig];
                af[i][2] = Ab[(r  )*CWS + w0 + tig + 4];
                af[i][3] = Ab[(r+8)*CWS + w0 + tig + 4];
            }
            #pragma unroll
            for (int j = 0; j < 4; j++) {
                int n = wn*32 + j*8 + g;
                bf[j][0] = Bb[n*CWS + w0 + tig];
                bf[j][1] = Bb[n*CWS + w0 + tig + 4];
            }
            #pragma unroll
            for (int i = 0; i < 4; i++)
                #pragma unroll
                for (int j = 0; j < 4; j++)
                    mma_f16(acc[i][j], af[i], bf[j][0], bf[j][1]);
        }
        __syncthreads();
    }

    #pragma unroll
    for (int i = 0; i < 4; i++) {
        int r = m0 + wm*64 + i*16 + g;
        #pragma unroll
        for (int j = 0; j < 4; j++) {
            int cc = n0 + wn*32 + j*8 + tig*2;
            float b0 = bias[cc], b1 = bias[cc+1];
            *(__half2*)&g_hh[(size_t)r*512 + cc]     = __floats2half2_rn(acc[i][j][0] + b0, acc[i][j][1] + b1);
            *(__half2*)&g_hh[(size_t)(r+8)*512 + cc] = __floats2half2_rn(acc[i][j][2] + b0, acc[i][j][3] + b1);
        }
    }
}

// =================================================================
// Flash attention, fp16 m16n8k16, KV tile 96 rows (6 tiles).
//   Qs/KV stride 36 words; P stride 52 words (both conflict-free).
// =================================================================
#define AWS 36
#define PWA 52
#define KT  96
#define KV_OFF   (96*AWS)                 // Qs 96x36
#define PS_OFF   (KV_OFF + 2*KT*AWS)      // KV 2x96x36
#define MS_OFF   (PS_OFF + 96*PWA)        // P 96x52
#define SS_OFF   (MS_OFF + 192)
#define ATTN_SMEM ((SS_OFF + 192)*4)      // 62976 B

__global__ __launch_bounds__(192, 3) void attn_f16() {
    extern __shared__ float sm[];
    uint32_t* QW = (uint32_t*)sm;
    uint32_t* KVW = QW + KV_OFF;
    uint32_t* PW = QW + PS_OFF;
    float* Msm = sm + MS_OFF;
    float* Ssm = sm + SS_OFF;

    const int qt = blockIdx.x, hh = blockIdx.y, b = blockIdx.z;
    const int tid = threadIdx.x;
    const int wr = tid >> 5, lane = tid & 31;
    const int wm = wr >> 1, wn = wr & 1;
    const int g = lane >> 2, tig = lane & 3;
    const size_t rowbase = (size_t)(b*SLEN)*EMB_ + hh*HD;
    const int rr[2] = { wm*32 + g, wm*32 + 16 + g };

    const int lm_row  = lane & 15;
    const int lm_colw = ((lane >> 4) & 1) * 4 + wn*16;

    auto loadKV = [&](int buf, int kt) {
        const __half* kb = g_hh + rowbase + (size_t)(kt*KT)*EMB_;
        for (int v = tid; v < KT*8; v += 192) {
            int r = v >> 3, c8 = (v & 7);
            cp_async16(&KVW[buf*KT*AWS + r*AWS + c8*4], kb + (size_t)r*EMB_ + c8*8);
        }
    };

    // prologue: KV tile 0 -> buf0, H -> QW, G -> PW (stride 52)
    loadKV(0, 0);
    {
        const __half* hb = g_hh + rowbase + (size_t)(qt*96)*EMB_;
        for (int v = tid; v < 768; v += 192) {
            int r = v >> 3, c8 = (v & 7);
            cp_async16(&QW[r*AWS + c8*4], hb + (size_t)r*EMB_ + c8*8);
        }
        for (int v = tid; v < 512; v += 192) {
            int r = v >> 3, c8 = (v & 7);
            cp_async16(&PW[r*PWA + c8*4], g_Gh + r*64 + c8*8);
        }
    }
    CP_COMMIT();
    CP_WAIT(0);
    __syncthreads();

    // ---- Q = H @ G ----
    {
        float qc[2][4][4] = {};
        #pragma unroll
        for (int ks = 0; ks < 4; ks++) {
            int w0 = ks*8;
            uint32_t ha[2][4];
            #pragma unroll
            for (int i = 0; i < 2; i++) {
                ha[i][0] = QW[(rr[i]  )*AWS + w0 + tig];
                ha[i][1] = QW[(rr[i]+8)*AWS + w0 + tig];
                ha[i][2] = QW[(rr[i]  )*AWS + w0 + tig + 4];
                ha[i][3] = QW[(rr[i]+8)*AWS + w0 + tig + 4];
            }
            #pragma unroll
            for (int j = 0; j < 4; j++) {
                int n = wn*32 + j*8 + g;
                uint32_t b0 = PW[n*PWA + w0 + tig];
                uint32_t b1 = PW[n*PWA + w0 + tig + 4];
                mma_f16(qc[0][j], ha[0], b0, b1);
                mma_f16(qc[1][j], ha[1], b0, b1);
            }
        }
        __syncthreads();   // done reading H (QW) and G (PW)
        #pragma unroll
        for (int i = 0; i < 2; i++)
            #pragma unroll
            for (int j = 0; j < 4; j++) {
                int cw = wn*16 + j*4 + tig;
                QW[(rr[i]  )*AWS + cw] = pack2(qc[i][j][0], qc[i][j][1]);
                QW[(rr[i]+8)*AWS + cw] = pack2(qc[i][j][2], qc[i][j][3]);
            }
        __syncthreads();
    }

    float oacc[2][4][4] = {};
    float m_[2][2], l_[2][2];
    #pragma unroll
    for (int i = 0; i < 2; i++) { m_[i][0] = m_[i][1] = -3.0e38f; l_[i][0] = l_[i][1] = 0.f; }

    const uint32_t kv_base_addr = (uint32_t)__cvta_generic_to_shared(KVW);

    for (int kt = 0; kt < 6; kt++) {
        int buf = kt & 1;
        CP_WAIT(0);
        __syncthreads();

        if (kt + 1 < 6) { loadKV(buf ^ 1, kt + 1); CP_COMMIT(); }

        const uint32_t* KB = KVW + buf*KT*AWS;
        const uint32_t kaddr = kv_base_addr + (buf*KT*AWS)*4;

        // ---- S = Q K^T : warp covers 48 of 96 l-cols ----
        float sacc[2][6][4] = {};
        #pragma unroll
        for (int ks = 0; ks < 4; ks++) {
            int w0 = ks*8;
            uint32_t a0[4], a1[4];
            a0[0] = QW[(rr[0]  )*AWS + w0 + tig];
            a0[1] = QW[(rr[0]+8)*AWS + w0 + tig];
            a0[2] = QW[(rr[0]  )*AWS + w0 + tig + 4];
            a0[3] = QW[(rr[0]+8)*AWS + w0 + tig + 4];
            a1[0] = QW[(rr[1]  )*AWS + w0 + tig];
            a1[1] = QW[(rr[1]+8)*AWS + w0 + tig];
            a1[2] = QW[(rr[1]  )*AWS + w0 + tig + 4];
            a1[3] = QW[(rr[1]+8)*AWS + w0 + tig + 4];
            #pragma unroll
            for (int j = 0; j < 6; j++) {
                int l = wn*48 + j*8 + g;
                uint32_t b0 = KB[l*AWS + w0 + tig];
                uint32_t b1 = KB[l*AWS + w0 + tig + 4];
                mma_f16(sacc[0][j], a0, b0, b1);
                mma_f16(sacc[1][j], a1, b0, b1);
            }
        }

        // ---- partial row max over 6 j-tiles, quad-reduce, exchange ----
        float pm[2][2];
        #pragma unroll
        for (int i = 0; i < 2; i++) {
            pm[i][0] = -3.0e38f; pm[i][1] = -3.0e38f;
            #pragma unroll
            for (int j = 0; j < 6; j++) {
                pm[i][0] = fmaxf(pm[i][0], fmaxf(sacc[i][j][0], sacc[i][j][1]));
                pm[i][1] = fmaxf(pm[i][1], fmaxf(sacc[i][j][2], sacc[i][j][3]));
            }
            #pragma unroll
            for (int r = 0; r < 2; r++) {
                pm[i][r] = fmaxf(pm[i][r], __shfl_xor_sync(0xffffffffu, pm[i][r], 1));
                pm[i][r] = fmaxf(pm[i][r], __shfl_xor_sync(0xffffffffu, pm[i][r], 2));
            }
        }
        if (tig == 0) {
            #pragma unroll
            for (int i = 0; i < 2; i++) {
                Msm[(rr[i]  )*2 + wn] = pm[i][0];
                Msm[(rr[i]+8)*2 + wn] = pm[i][1];
            }
        }
        __syncthreads();

        float alpha[2][2];
        #pragma unroll
        for (int i = 0; i < 2; i++) {
            #pragma unroll
            for (int r = 0; r < 2; r++) {
                int row = rr[i] + r*8;
                float mt = fmaxf(Msm[row*2], Msm[row*2 + 1]);
                float mnew = fmaxf(m_[i][r], mt);
                alpha[i][r] = __expf(m_[i][r] - mnew);
                m_[i][r] = mnew;
            }
        }

        // ---- p = exp(s-m) -> PW (stride 52), partial sums, exchange ----
        float psum[2][2] = {};
        #pragma unroll
        for (int i = 0; i < 2; i++)
            #pragma unroll
            for (int j = 0; j < 6; j++) {
                int cw = wn*24 + j*4 + tig;
                float p0 = __expf(sacc[i][j][0] - m_[i][0]);
                float p1 = __expf(sacc[i][j][1] - m_[i][0]);
                float p2 = __expf(sacc[i][j][2] - m_[i][1]);
                float p3 = __expf(sacc[i][j][3] - m_[i][1]);
                psum[i][0] += p0 + p1;
                psum[i][1] += p2 + p3;
                PW[(rr[i]  )*PWA + cw] = pack2(p0, p1);
                PW[(rr[i]+8)*PWA + cw] = pack2(p2, p3);
            }
        #pragma unroll
        for (int i = 0; i < 2; i++)
            #pragma unroll
            for (int r = 0; r < 2; r++) {
                psum[i][r] += __shfl_xor_sync(0xffffffffu, psum[i][r], 1);
                psum[i][r] += __shfl_xor_sync(0xffffffffu, psum[i][r], 2);
            }
        if (tig == 0) {
            #pragma unroll
            for (int i = 0; i < 2; i++) {
                Ssm[(rr[i]  )*2 + wn] = psum[i][0];
                Ssm[(rr[i]+8)*2 + wn] = psum[i][1];
            }
        }
        __syncthreads();

        #pragma unroll
        for (int i = 0; i < 2; i++) {
            #pragma unroll
            for (int r = 0; r < 2; r++) {
                int row = rr[i] + r*8;
                l_[i][r] = l_[i][r]*alpha[i][r] + Ssm[row*2] + Ssm[row*2 + 1];
            }
            #pragma unroll
            for (int j = 0; j < 4; j++) {
                oacc[i][j][0] *= alpha[i][0]; oacc[i][j][1] *= alpha[i][0];
                oacc[i][j][2] *= alpha[i][1]; oacc[i][j][3] *= alpha[i][1];
            }
        }

        // ---- O += P V : 6 ks steps over 96 l ----
        #pragma unroll
        for (int ks = 0; ks < 6; ks++) {
            int w0 = ks*8;
            uint32_t ap[2][4];
            #pragma unroll
            for (int i = 0; i < 2; i++) {
                ap[i][0] = PW[(rr[i]  )*PWA + w0 + tig];
                ap[i][1] = PW[(rr[i]+8)*PWA + w0 + tig];
                ap[i][2] = PW[(rr[i]  )*PWA + w0 + tig + 4];
                ap[i][3] = PW[(rr[i]+8)*PWA + w0 + tig + 4];
            }
            #pragma unroll
            for (int jp = 0; jp < 2; jp++) {
                uint32_t r0, r1, r2, r3;
                uint32_t addr = kaddr + ((ks*16 + lm_row)*AWS + lm_colw + jp*8)*4;
                ldsm_x4_trans(r0, r1, r2, r3, addr);
                mma_f16(oacc[0][jp*2    ], ap[0], r0, r1);
                mma_f16(oacc[1][jp*2    ], ap[1], r0, r1);
                mma_f16(oacc[0][jp*2 + 1], ap[0], r2, r3);
                mma_f16(oacc[1][jp*2 + 1], ap[1], r2, r3);
            }
        }
    }

    __half* ob = g_ctxh + rowbase + (size_t)(qt*96)*EMB_;
    #pragma unroll
    for (int i = 0; i < 2; i++)
        #pragma unroll
        for (int r = 0; r < 2; r++) {
            int row = rr[i] + r*8;
            float inv = 1.0f / l_[i][r];
            #pragma unroll
            for (int j = 0; j < 4; j++) {
                int d = wn*32 + j*8 + tig*2;
                *(__half2*)&ob[(size_t)row*EMB_ + d] =
                    __floats2half2_rn(oacc[i][j][r*2]*inv, oacc[i][j][r*2+1]*inv);
            }
        }
}

// =================================================================
// Output projection, fp16, BK=64 halves. M=18432, N=512, K=512.
// =================================================================
#define PWS 36
#define PROJ_SMEM (2*128*PWS*2*4)   // 73728 B

__global__ __launch_bounds__(256, 2) void proj_f16(const float* __restrict__ bias,
                                                   float* __restrict__ C) {
    extern __shared__ float sm[];
    uint32_t* AW = (uint32_t*)sm;
    uint32_t* BW = AW + 2*128*PWS;

    const int tid = threadIdx.x;
    const int lane = tid & 31;
    const int wr = tid >> 5, wm = wr & 1, wn = wr >> 1;
    const int g = lane >> 2, tig = lane & 3;
    const int m0 = blockIdx.y * 128, n0 = blockIdx.x * 128;

    auto load_tiles = [&](int buf, int t) {
        #pragma unroll
        for (int i = 0; i < 4; i++) {
            int v = tid + i*256;
            int row = v >> 3, kc = v & 7;
            cp_async16(&AW[buf*128*PWS + row*PWS + kc*4],
                       g_ctxh + (size_t)(m0 + row)*512 + t*64 + kc*8);
            cp_async16(&BW[buf*128*PWS + row*PWS + kc*4],
                       g_WvoTh + (size_t)(n0 + row)*512 + t*64 + kc*8);
        }
    };

    float acc[4][4][4] = {};

    load_tiles(0, 0);
    CP_COMMIT();
    const int nk = 8;
    for (int t = 0; t < nk; t++) {
        int buf = t & 1;
        if (t + 1 < nk) load_tiles(buf ^ 1, t+1);
        CP_COMMIT();
        CP_WAIT(1);
        __syncthreads();

        const uint32_t* Ab = AW + buf*128*PWS;
        const uint32_t* Bb = BW + buf*128*PWS;
        #pragma unroll
        for (int ks = 0; ks < 4; ks++) {
            int w0 = ks*8;
            uint32_t af[4][4], bf[4][2];
            #pragma unroll
            for (int i = 0; i < 4; i++) {
                int r = wm*64 + i*16 + g;
                af[i][0] = Ab[(r  )*PWS + w0 + tig];
                af[i][1] = Ab[(r+8)*PWS + w0 + tig];
                af[i][2] = Ab[(r  )*PWS + w0 + tig + 4];
                af[i][3] = Ab[(r+8)*PWS + w0 + tig + 4];
            }
            #pragma unroll
            for (int j = 0; j < 4; j++) {
                int n = wn*32 + j*8 + g;
                bf[j][0] = Bb[n*PWS + w0 + tig];
                bf[j][1] = Bb[n*PWS + w0 + tig + 4];
            }
            #pragma unroll
            for (int i = 0; i < 4; i++)
                #pragma unroll
                for (int j = 0; j < 4; j++)
                    mma_f16(acc[i][j], af[i], bf[j][0], bf[j][1]);
        }
        __syncthreads();
    }

    #pragma unroll
    for (int i = 0; i < 4; i++) {
        int r = m0 + wm*64 + i*16 + g;
        #pragma unroll
        for (int j = 0; j < 4; j++) {
            int cc = n0 + wn*32 + j*8 + tig*2;
            float2 v0 = make_float2(acc[i][j][0] + bias[cc], acc[i][j][1] + bias[cc+1]);
            float2 v1 = make_float2(acc[i][j][2] + bias[cc], acc[i][j][3] + bias[cc+1]);
            *(float2*)&C[(size_t)r*512 + cc] = v0;
            *(float2*)&C[(size_t)(r+8)*512 + cc] = v1;
        }
    }
}

// =================================================================
extern "C" void kernel_launch(void* const* d_in, const int* in_sizes, int n_in,
                              void* d_out, int out_size) {
    (void)in_sizes; (void)n_in; (void)out_size;
    const float* x      = (const float*)d_in[0];
    const float* conv_w = (const float*)d_in[1];
    const float* conv_b = (const float*)d_in[2];
    const float* wq     = (const float*)d_in[3];
    const float* wk     = (const float*)d_in[4];
    const float* wv     = (const float*)d_in[5];
    const float* wo     = (const float*)d_in[6];
    const float* bo     = (const float*)d_in[7];
    float* out = (float*)d_out;

    cudaFuncSetAttribute(conv_f16, cudaFuncAttributeMaxDynamicSharedMemorySize, CONV_SMEM);
    cudaFuncSetAttribute(attn_f16, cudaFuncAttributeMaxDynamicSharedMemorySize, ATTN_SMEM);
    cudaFuncSetAttribute(proj_f16, cudaFuncAttributeMaxDynamicSharedMemorySize, PROJ_SMEM);

    x2h       <<<XELEM/(512*8), 512>>>(x);
    prep_convw<<<EMB_*KCONV/1024, 512>>>(conv_w);
    prep_G    <<<64, 64>>>(wq, wk);
    prep_Wvo  <<<512, 256>>>(wv, wo);
    conv_f16  <<<dim3(4, 144), 256, CONV_SMEM>>>(conv_b);
    attn_f16  <<<dim3(6, NHEAD, BATCH), 192, ATTN_SMEM>>>();
    proj_f16  <<<dim3(4, 144), 256, PROJ_SMEM>>>(bo, out);
}